// round 1
// baseline (speedup 1.0000x reference)
#include <cuda_runtime.h>
#include <cstddef>

#define Bn 2
#define Tn 2048
#define En 1024
#define Hn 16
#define HDn 64
#define FFn 4096
#define Mn (Bn*Tn)          // 4096 rows
#define QKVN (3*En)         // 3072

// ---------------- scratch (device globals; allocation-free) ----------------
__device__ float g_h1[(size_t)Mn*En];          // LN1 out           16 MB
__device__ float g_wqkv[(size_t)En*QKVN];      // packed QKV weight 12 MB
__device__ float g_qkv[(size_t)Mn*QKVN];       // Q|K|V concat      48 MB
__device__ float g_attno[(size_t)Mn*En];       // attention out     16 MB
__device__ float g_x2[(size_t)Mn*En];          // x + proj          16 MB
__device__ float g_h2[(size_t)Mn*En];          // LN2 out           16 MB
__device__ float g_mid[(size_t)Mn*FFn];        // FFN hidden        64 MB

// ---------------- weight packer: (H,E,HD)x3 -> [E, 3*H*HD] ----------------
__global__ void pack_w_kernel(const float* __restrict__ Wq,
                              const float* __restrict__ Wk,
                              const float* __restrict__ Wv,
                              float* __restrict__ out) {
    int i = blockIdx.x * 256 + threadIdx.x;          // over En*QKVN
    if (i >= En * QKVN) return;
    int d  = i / QKVN;
    int c  = i % QKVN;
    int s  = c / En;          // 0=q 1=k 2=v
    int hc = c % En;
    int h  = hc / HDn, e = hc % HDn;
    const float* W = (s == 0) ? Wq : (s == 1) ? Wk : Wv;
    out[i] = W[((size_t)h * En + d) * HDn + e];
}

// ---------------- LayerNorm: one block per row of E=1024 ----------------
__global__ void ln_kernel(const float* __restrict__ x, const float* __restrict__ g,
                          const float* __restrict__ b, float* __restrict__ out) {
    int row = blockIdx.x;
    const float* xr = x + (size_t)row * En;
    float v[4];
    float s = 0.f, sq = 0.f;
#pragma unroll
    for (int i = 0; i < 4; i++) {
        v[i] = xr[threadIdx.x + i * 256];
        s += v[i]; sq += v[i] * v[i];
    }
    __shared__ float red[18];
#pragma unroll
    for (int o = 16; o; o >>= 1) {
        s  += __shfl_xor_sync(0xFFFFFFFFu, s,  o);
        sq += __shfl_xor_sync(0xFFFFFFFFu, sq, o);
    }
    int w = threadIdx.x >> 5, l = threadIdx.x & 31;
    if (l == 0) { red[w] = s; red[8 + w] = sq; }
    __syncthreads();
    if (threadIdx.x == 0) {
        float ts = 0.f, tq = 0.f;
#pragma unroll
        for (int i = 0; i < 8; i++) { ts += red[i]; tq += red[8 + i]; }
        red[16] = ts; red[17] = tq;
    }
    __syncthreads();
    float mean = red[16] * (1.f / En);
    float var  = red[17] * (1.f / En) - mean * mean;
    float rstd = rsqrtf(var + 1e-5f);
    float* outr = out + (size_t)row * En;
#pragma unroll
    for (int i = 0; i < 4; i++) {
        int c = threadIdx.x + i * 256;
        outr[c] = (v[i] - mean) * rstd * g[c] + b[c];
    }
}

// ---------------- SGEMM: C[M,N] = A[M,K] @ B[K,N] (+epilogue) ----------------
// BM=BN=64, BK=16, 256 threads, 4x4 per-thread microtile.
// EPI: 0=none, 1=+bias[n]+res[m,n], 2=relu(+bias[n])
template<int EPI>
__global__ void __launch_bounds__(256)
sgemm_kernel(const float* __restrict__ A, const float* __restrict__ Bm,
             float* __restrict__ C, int M, int N, int K,
             const float* __restrict__ bias, const float* __restrict__ res) {
    __shared__ float As[16][64];     // transposed A tile: As[k][m]
    __shared__ float Bs[16][64];     // Bs[k][n]
    int tid  = threadIdx.x;
    int tx   = tid & 15, ty = tid >> 4;
    int brow = blockIdx.y * 64, bcol = blockIdx.x * 64;

    float acc[4][4];
#pragma unroll
    for (int i = 0; i < 4; i++)
#pragma unroll
        for (int j = 0; j < 4; j++) acc[i][j] = 0.f;

    int arow  = tid >> 2, acol = (tid & 3) * 4;   // A: 64 rows x 16 cols, float4/thread
    int bkrow = tid >> 4, bcol4 = (tid & 15) * 4; // B: 16 rows x 64 cols, float4/thread
    const float* Aptr = A  + (size_t)(brow + arow)  * K + acol;
    const float* Bptr = Bm + (size_t)bkrow * N + bcol + bcol4;

    for (int k0 = 0; k0 < K; k0 += 16) {
        float4 av = *(const float4*)Aptr;
        float4 bv = *(const float4*)Bptr;
        As[acol + 0][arow] = av.x;
        As[acol + 1][arow] = av.y;
        As[acol + 2][arow] = av.z;
        As[acol + 3][arow] = av.w;
        *(float4*)&Bs[bkrow][bcol4] = bv;
        __syncthreads();
#pragma unroll
        for (int k = 0; k < 16; k++) {
            float4 a = *(const float4*)&As[k][ty * 4];
            float4 b = *(const float4*)&Bs[k][tx * 4];
            float aa[4] = {a.x, a.y, a.z, a.w};
            float bb[4] = {b.x, b.y, b.z, b.w};
#pragma unroll
            for (int i = 0; i < 4; i++)
#pragma unroll
                for (int j = 0; j < 4; j++) acc[i][j] += aa[i] * bb[j];
        }
        __syncthreads();
        Aptr += 16;
        Bptr += (size_t)16 * N;
    }

#pragma unroll
    for (int i = 0; i < 4; i++) {
        int r = brow + ty * 4 + i;
#pragma unroll
        for (int j = 0; j < 4; j++) {
            int c = bcol + tx * 4 + j;
            float v = acc[i][j];
            if (EPI == 1) v = v + bias[c] + res[(size_t)r * N + c];
            if (EPI == 2) { v += bias[c]; v = v > 0.f ? v : 0.f; }
            C[(size_t)r * N + c] = v;
        }
    }
}

// ---------------- flash attention (causal, scale = E^-0.5 = 1/32) ----------------
// grid: (T/64 qtiles, B*H). block 256 = 8 warps; warp owns 8 query rows;
// lane owns keys {l, l+32} for scores, dims {l, l+32} for output accumulation.
__global__ void __launch_bounds__(256)
attn_kernel(const float* __restrict__ qkv, float* __restrict__ out) {
    extern __shared__ float sm[];
    float* Qs = sm;                  // [64][64]
    float* Ks = Qs + 64 * 64;        // [64][65]  padded
    float* Vs = Ks + 64 * 65;        // [64][64]
    float* Ps = Vs + 64 * 64;        // [8][64]   per-warp probabilities

    int bh = blockIdx.y;
    int b = bh / Hn, h = bh % Hn;
    int q0 = blockIdx.x * 64;
    int tid = threadIdx.x;
    int w = tid >> 5, l = tid & 31;

    const size_t rs = QKVN;          // row stride in g_qkv
    const float* Qg = qkv + ((size_t)b * Tn + q0) * rs + h * HDn;
    const float* Kg = qkv + ((size_t)b * Tn) * rs + En + h * HDn;
    const float* Vg = Kg + En;

    // load Q tile
#pragma unroll
    for (int it = 0; it < 16; it++) {
        int idx = it * 256 + tid;
        int r = idx >> 6, d = idx & 63;
        Qs[r * 64 + d] = Qg[(size_t)r * rs + d];
    }

    float m[8], ssum[8], o0[8], o1[8];
#pragma unroll
    for (int r = 0; r < 8; r++) { m[r] = -1e30f; ssum[r] = 0.f; o0[r] = 0.f; o1[r] = 0.f; }

    for (int j0 = 0; j0 <= q0; j0 += 64) {
        __syncthreads();
#pragma unroll
        for (int it = 0; it < 16; it++) {
            int idx = it * 256 + tid;
            int r = idx >> 6, d = idx & 63;
            Ks[r * 65 + d] = Kg[((size_t)j0 + r) * rs + d];
            Vs[r * 64 + d] = Vg[((size_t)j0 + r) * rs + d];
        }
        __syncthreads();
        bool lastChunk = (j0 == q0);

#pragma unroll
        for (int r = 0; r < 8; r++) {
            int qg = q0 + w * 8 + r;
            const float* qrow = &Qs[(w * 8 + r) * 64];
            float s0 = 0.f, s1 = 0.f;
#pragma unroll 16
            for (int d = 0; d < 64; d++) {
                float qd = qrow[d];
                s0 += qd * Ks[l * 65 + d];
                s1 += qd * Ks[(l + 32) * 65 + d];
            }
            s0 *= 0.03125f; s1 *= 0.03125f;
            if (lastChunk) {
                if (j0 + l      > qg) s0 = -1e30f;
                if (j0 + l + 32 > qg) s1 = -1e30f;
            }
            float mc = fmaxf(s0, s1);
#pragma unroll
            for (int o = 16; o; o >>= 1) mc = fmaxf(mc, __shfl_xor_sync(0xFFFFFFFFu, mc, o));
            float mn = fmaxf(m[r], mc);
            float alpha = __expf(m[r] - mn);
            float p0 = __expf(s0 - mn), p1 = __expf(s1 - mn);
            float ps = p0 + p1;
#pragma unroll
            for (int o = 16; o; o >>= 1) ps += __shfl_xor_sync(0xFFFFFFFFu, ps, o);
            ssum[r] = ssum[r] * alpha + ps;
            m[r] = mn;
            o0[r] *= alpha; o1[r] *= alpha;
            Ps[w * 64 + l]      = p0;
            Ps[w * 64 + l + 32] = p1;
            __syncwarp();
            float a0 = 0.f, a1 = 0.f;
#pragma unroll 16
            for (int kk = 0; kk < 64; kk++) {
                float p = Ps[w * 64 + kk];
                a0 += p * Vs[kk * 64 + l];
                a1 += p * Vs[kk * 64 + l + 32];
            }
            o0[r] += a0; o1[r] += a1;
            __syncwarp();
        }
    }

#pragma unroll
    for (int r = 0; r < 8; r++) {
        int qg = q0 + w * 8 + r;
        float inv = 1.0f / ssum[r];
        size_t base = ((size_t)b * Tn + qg) * En + h * HDn;
        out[base + l]      = o0[r] * inv;
        out[base + l + 32] = o1[r] * inv;
    }
}

// ---------------- launch ----------------
extern "C" void kernel_launch(void* const* d_in, const int* in_sizes, int n_in,
                              void* d_out, int out_size) {
    const float* x     = (const float*)d_in[0];
    const float* Wq    = (const float*)d_in[1];
    const float* Wk    = (const float*)d_in[2];
    const float* Wv    = (const float*)d_in[3];
    const float* Wproj = (const float*)d_in[4];
    const float* bproj = (const float*)d_in[5];
    const float* W1    = (const float*)d_in[6];
    const float* b1    = (const float*)d_in[7];
    const float* W2    = (const float*)d_in[8];
    const float* b2    = (const float*)d_in[9];
    const float* g1    = (const float*)d_in[10];
    const float* be1   = (const float*)d_in[11];
    const float* g2    = (const float*)d_in[12];
    const float* be2   = (const float*)d_in[13];
    float* out = (float*)d_out;

    float *h1, *wqkv, *qkv, *attno, *x2, *h2, *mid;
    cudaGetSymbolAddress((void**)&h1,    g_h1);
    cudaGetSymbolAddress((void**)&wqkv,  g_wqkv);
    cudaGetSymbolAddress((void**)&qkv,   g_qkv);
    cudaGetSymbolAddress((void**)&attno, g_attno);
    cudaGetSymbolAddress((void**)&x2,    g_x2);
    cudaGetSymbolAddress((void**)&h2,    g_h2);
    cudaGetSymbolAddress((void**)&mid,   g_mid);

    const int ATTN_SMEM = (64 * 64 + 64 * 65 + 64 * 64 + 8 * 64) * 4; // 51456 B
    cudaFuncSetAttribute(attn_kernel, cudaFuncAttributeMaxDynamicSharedMemorySize, ATTN_SMEM);

    // 1. pack QKV weights -> [E, 3*H*HD]
    pack_w_kernel<<<(En * QKVN + 255) / 256, 256>>>(Wq, Wk, Wv, wqkv);
    // 2. LN1
    ln_kernel<<<Mn, 256>>>(x, g1, be1, h1);
    // 3. QKV GEMM: [4096,1024] @ [1024,3072]
    sgemm_kernel<0><<<dim3(QKVN / 64, Mn / 64), 256>>>(h1, wqkv, qkv, Mn, QKVN, En, nullptr, nullptr);
    // 4. causal flash attention
    attn_kernel<<<dim3(Tn / 64, Bn * Hn), 256, ATTN_SMEM>>>(qkv, attno);
    // 5. output proj + bias + residual(x)
    sgemm_kernel<1><<<dim3(En / 64, Mn / 64), 256>>>(attno, Wproj, x2, Mn, En, En, bproj, x);
    // 6. LN2
    ln_kernel<<<Mn, 256>>>(x2, g2, be2, h2);
    // 7. FFN1: relu(h2 @ W1 + b1)
    sgemm_kernel<2><<<dim3(FFn / 64, Mn / 64), 256>>>(h2, W1, mid, Mn, FFn, En, b1, nullptr);
    // 8. FFN2: x2 + mid @ W2 + b2 -> out
    sgemm_kernel<1><<<dim3(En / 64, Mn / 64), 256>>>(mid, W2, out, Mn, En, FFn, b2, x2);
}

// round 3
// speedup vs baseline: 1.6966x; 1.6966x over previous
#include <cuda_runtime.h>
#include <cuda_bf16.h>
#include <cstdint>
#include <cstddef>

#define Bn 2
#define Tn 2048
#define En 1024
#define Hn 16
#define HDn 64
#define FFn 4096
#define Mn (Bn*Tn)          // 4096
#define QKVN (3*En)         // 3072

// ---------------- scratch (device globals) ----------------
__device__ float g_qkv[(size_t)Mn*QKVN];                       // 48 MB fp32
__device__ float g_x2[(size_t)Mn*En];                          // 16 MB fp32
__device__ __nv_bfloat16 g_h1h[(size_t)Mn*En],  g_h1l[(size_t)Mn*En];
__device__ __nv_bfloat16 g_h2h[(size_t)Mn*En],  g_h2l[(size_t)Mn*En];
__device__ __nv_bfloat16 g_aoh[(size_t)Mn*En],  g_aol[(size_t)Mn*En];
__device__ __nv_bfloat16 g_midh[(size_t)Mn*FFn], g_midl[(size_t)Mn*FFn];
__device__ __nv_bfloat16 g_wqkvh[(size_t)QKVN*En], g_wqkvl[(size_t)QKVN*En];
__device__ __nv_bfloat16 g_wph[(size_t)En*En],   g_wpl[(size_t)En*En];
__device__ __nv_bfloat16 g_w1h[(size_t)FFn*En],  g_w1l[(size_t)FFn*En];
__device__ __nv_bfloat16 g_w2h[(size_t)En*FFn],  g_w2l[(size_t)En*FFn];

// ---------------- helpers ----------------
__device__ __forceinline__ void split_bf16(float v, __nv_bfloat16& h, __nv_bfloat16& l) {
    h = __float2bfloat16(v);
    l = __float2bfloat16(v - __bfloat162float(h));
}

__device__ __forceinline__ uint32_t s2u(const void* p) {
    uint32_t a;
    asm("{ .reg .u64 t; cvta.to.shared.u64 t, %1; cvt.u32.u64 %0, t; }" : "=r"(a) : "l"(p));
    return a;
}

__device__ __forceinline__ void cp16(uint32_t s, const void* g) {
    asm volatile("cp.async.cg.shared.global [%0], [%1], 16;" :: "r"(s), "l"(g));
}
#define CP_COMMIT() asm volatile("cp.async.commit_group;")
#define CP_WAIT(N)  asm volatile("cp.async.wait_group %0;" :: "n"(N))

#define LDM4(r, addr) \
    asm volatile("ldmatrix.sync.aligned.m8n8.x4.shared.b16 {%0,%1,%2,%3}, [%4];" \
        : "=r"((r)[0]), "=r"((r)[1]), "=r"((r)[2]), "=r"((r)[3]) : "r"(addr))

#define MMA_BF16(d, a, b0, b1) \
    asm volatile("mma.sync.aligned.m16n8k16.row.col.f32.bf16.bf16.f32 " \
        "{%0,%1,%2,%3}, {%4,%5,%6,%7}, {%8,%9}, {%0,%1,%2,%3};" \
        : "+f"((d)[0]), "+f"((d)[1]), "+f"((d)[2]), "+f"((d)[3]) \
        : "r"((a)[0]), "r"((a)[1]), "r"((a)[2]), "r"((a)[3]), "r"(b0), "r"(b1))

// ---------------- weight pack kernels ----------------
__global__ void pack_qkv_kernel(const float* __restrict__ Wq, const float* __restrict__ Wk,
                                const float* __restrict__ Wv,
                                __nv_bfloat16* __restrict__ oh, __nv_bfloat16* __restrict__ ol) {
    int i = blockIdx.x * 256 + threadIdx.x;          // over QKVN*En
    if (i >= QKVN * En) return;
    int n = i / En, k = i % En;
    int sel = n >> 10;                // 0=q 1=k 2=v
    int hc = n & 1023;
    int h = hc >> 6, e = hc & 63;
    const float* W = (sel == 0) ? Wq : (sel == 1) ? Wk : Wv;
    float v = W[((size_t)h * En + k) * HDn + e];
    __nv_bfloat16 hi, lo; split_bf16(v, hi, lo);
    oh[i] = hi; ol[i] = lo;
}

// transpose + split: In [K, N] -> out [N, K]
__global__ void pack_t_kernel(const float* __restrict__ In,
                              __nv_bfloat16* __restrict__ oh, __nv_bfloat16* __restrict__ ol,
                              int K, int N) {
    int i = blockIdx.x * 256 + threadIdx.x;          // over N*K
    if (i >= N * K) return;
    int n = i / K, k = i % K;
    float v = In[(size_t)k * N + n];
    __nv_bfloat16 hi, lo; split_bf16(v, hi, lo);
    oh[i] = hi; ol[i] = lo;
}

// ---------------- LayerNorm: fp32 in -> bf16 hi/lo out ----------------
__global__ void ln_kernel(const float* __restrict__ x, const float* __restrict__ g,
                          const float* __restrict__ b,
                          __nv_bfloat16* __restrict__ oh, __nv_bfloat16* __restrict__ ol) {
    int row = blockIdx.x;
    const float* xr = x + (size_t)row * En;
    float v[4];
    float s = 0.f, sq = 0.f;
#pragma unroll
    for (int i = 0; i < 4; i++) {
        v[i] = xr[threadIdx.x + i * 256];
        s += v[i]; sq += v[i] * v[i];
    }
    __shared__ float red[18];
#pragma unroll
    for (int o = 16; o; o >>= 1) {
        s  += __shfl_xor_sync(0xFFFFFFFFu, s,  o);
        sq += __shfl_xor_sync(0xFFFFFFFFu, sq, o);
    }
    int w = threadIdx.x >> 5, l = threadIdx.x & 31;
    if (l == 0) { red[w] = s; red[8 + w] = sq; }
    __syncthreads();
    if (threadIdx.x == 0) {
        float ts = 0.f, tq = 0.f;
#pragma unroll
        for (int i = 0; i < 8; i++) { ts += red[i]; tq += red[8 + i]; }
        red[16] = ts; red[17] = tq;
    }
    __syncthreads();
    float mean = red[16] * (1.f / En);
    float var  = red[17] * (1.f / En) - mean * mean;
    float rstd = rsqrtf(var + 1e-5f);
#pragma unroll
    for (int i = 0; i < 4; i++) {
        int c = threadIdx.x + i * 256;
        float y = (v[i] - mean) * rstd * g[c] + b[c];
        __nv_bfloat16 hi, lo; split_bf16(y, hi, lo);
        oh[(size_t)row * En + c] = hi;
        ol[(size_t)row * En + c] = lo;
    }
}

// ---------------- mma.sync GEMM: C[M,N] = (Ah+Al)[M,K] @ (Bh+Bl)^T ([N,K]) ----------------
// CTA tile 128x128, BK=32, double-buffered cp.async. 256 threads = 8 warps (2x4),
// warp tile 64x32. Split precision: D = Ah*Bh + Ah*Bl + Al*Bh (fp32 accum).
// EPI: 0 = fp32 out; 1 = fp32 out + bias + residual; 2 = relu(+bias) -> bf16 hi/lo
template<int EPI>
__global__ void __launch_bounds__(256, 1)
mma_gemm(const __nv_bfloat16* __restrict__ Ah, const __nv_bfloat16* __restrict__ Al,
         const __nv_bfloat16* __restrict__ Bh, const __nv_bfloat16* __restrict__ Bl,
         int M, int N, int K,
         const float* __restrict__ bias, const float* __restrict__ res,
         float* __restrict__ Cf,
         __nv_bfloat16* __restrict__ Ch, __nv_bfloat16* __restrict__ Cl) {
    extern __shared__ __align__(1024) char smem[];
    // per stage (32KB): Ah@0, Al@8K, Bh@16K, Bl@24K; 2 stages
    const uint32_t su = s2u(smem);
    const int tid = threadIdx.x;
    const int lane = tid & 31, wid = tid >> 5;
    const int warp_m = wid & 1, warp_n = wid >> 1;
    const int brow = blockIdx.y * 128, bcol = blockIdx.x * 128;
    const int S = K >> 5;      // stages of BK=32

    // ldmatrix address constants
    const int mat = lane >> 3, rowm = lane & 7;
    const int c16bA = mat >> 1;      // A: matrix pairs split k-chunks
    const int c16bB = mat & 1;       // B: matrix pairs split k-chunks
    uint32_t mrow64[4], swmA[4];
#pragma unroll
    for (int mi = 0; mi < 4; mi++) {
        int m = warp_m * 64 + mi * 16 + (mat & 1) * 8 + rowm;
        mrow64[mi] = (uint32_t)(m * 64);
        swmA[mi] = (uint32_t)(((m >> 1) & 7) << 4);
    }
    uint32_t nrow64[2], swmB[2];
#pragma unroll
    for (int nj = 0; nj < 2; nj++) {
        int n = warp_n * 32 + nj * 16 + (mat >> 1) * 8 + rowm;
        nrow64[nj] = (uint32_t)(n * 64);
        swmB[nj] = (uint32_t)(((n >> 1) & 7) << 4);
    }

    float acc[4][4][4];
#pragma unroll
    for (int mi = 0; mi < 4; mi++)
#pragma unroll
        for (int j = 0; j < 4; j++)
#pragma unroll
            for (int r = 0; r < 4; r++) acc[mi][j][r] = 0.f;

    // stage loader: 128 rows x 32 cols bf16 per tensor, 4 tensors
    auto load_stage = [&](int s, int buf) {
        const int k0 = s * 32;
        const uint32_t sb = su + (uint32_t)buf * 32768;
#pragma unroll
        for (int i = 0; i < 2; i++) {
            int idx = tid + i * 256;          // 0..511
            int r = idx >> 2, c = idx & 3;    // row, 16B chunk
            uint32_t o = (uint32_t)(r * 64 + c * 16);
            uint32_t sw = o ^ (((o >> 7) & 7) << 4);
            size_t ao = (size_t)(brow + r) * K + k0 + c * 8;
            size_t bo = (size_t)(bcol + r) * K + k0 + c * 8;
            cp16(sb + sw,         Ah + ao);
            cp16(sb + 8192 + sw,  Al + ao);
            cp16(sb + 16384 + sw, Bh + bo);
            cp16(sb + 24576 + sw, Bl + bo);
        }
    };

    load_stage(0, 0);
    CP_COMMIT();

    for (int s = 0; s < S; s++) {
        if (s + 1 < S) { load_stage(s + 1, (s + 1) & 1); CP_COMMIT(); CP_WAIT(1); }
        else           { CP_WAIT(0); }
        __syncthreads();

        const uint32_t sb = su + (uint32_t)(s & 1) * 32768;
#pragma unroll
        for (int kk = 0; kk < 2; kk++) {
            uint32_t ah[4][4], al[4][4];
            const int cA = kk * 2 + c16bA;
#pragma unroll
            for (int mi = 0; mi < 4; mi++) {
                uint32_t oa = (mrow64[mi] + (uint32_t)(cA * 16)) ^ swmA[mi];
                LDM4(ah[mi], sb + oa);
                LDM4(al[mi], sb + 8192 + oa);
            }
            uint32_t bh[2][4], bl[2][4];
            const int cB = kk * 2 + c16bB;
#pragma unroll
            for (int nj = 0; nj < 2; nj++) {
                uint32_t ob = (nrow64[nj] + (uint32_t)(cB * 16)) ^ swmB[nj];
                LDM4(bh[nj], sb + 16384 + ob);
                LDM4(bl[nj], sb + 24576 + ob);
            }
#pragma unroll
            for (int mi = 0; mi < 4; mi++) {
#pragma unroll
                for (int j = 0; j < 4; j++) {
                    const int nj = j >> 1, rb = (j & 1) * 2;
                    MMA_BF16(acc[mi][j], ah[mi], bh[nj][rb], bh[nj][rb + 1]);
                    MMA_BF16(acc[mi][j], ah[mi], bl[nj][rb], bl[nj][rb + 1]);
                    MMA_BF16(acc[mi][j], al[mi], bh[nj][rb], bh[nj][rb + 1]);
                }
            }
        }
        __syncthreads();
    }

    // ---------------- epilogue ----------------
    const int rowbase = brow + warp_m * 64 + (lane >> 2);
    const int colbase = bcol + warp_n * 32 + (lane & 3) * 2;
#pragma unroll
    for (int mi = 0; mi < 4; mi++) {
#pragma unroll
        for (int j = 0; j < 4; j++) {
            int col = colbase + j * 8;
            int r0 = rowbase + mi * 16;
            int r1 = r0 + 8;
            float v00 = acc[mi][j][0], v01 = acc[mi][j][1];
            float v10 = acc[mi][j][2], v11 = acc[mi][j][3];
            if (EPI == 0) {
                *(float2*)(Cf + (size_t)r0 * N + col) = make_float2(v00, v01);
                *(float2*)(Cf + (size_t)r1 * N + col) = make_float2(v10, v11);
            } else if (EPI == 1) {
                float b0 = bias[col], b1 = bias[col + 1];
                const float2 rr0 = *(const float2*)(res + (size_t)r0 * N + col);
                const float2 rr1 = *(const float2*)(res + (size_t)r1 * N + col);
                *(float2*)(Cf + (size_t)r0 * N + col) = make_float2(v00 + b0 + rr0.x, v01 + b1 + rr0.y);
                *(float2*)(Cf + (size_t)r1 * N + col) = make_float2(v10 + b0 + rr1.x, v11 + b1 + rr1.y);
            } else {
                float b0 = bias[col], b1 = bias[col + 1];
                float w00 = fmaxf(v00 + b0, 0.f), w01 = fmaxf(v01 + b1, 0.f);
                float w10 = fmaxf(v10 + b0, 0.f), w11 = fmaxf(v11 + b1, 0.f);
                __nv_bfloat16 h00, l00, h01, l01, h10, l10, h11, l11;
                split_bf16(w00, h00, l00); split_bf16(w01, h01, l01);
                split_bf16(w10, h10, l10); split_bf16(w11, h11, l11);
                *(__nv_bfloat162*)(Ch + (size_t)r0 * N + col) = __halves2bfloat162(h00, h01);
                *(__nv_bfloat162*)(Cl + (size_t)r0 * N + col) = __halves2bfloat162(l00, l01);
                *(__nv_bfloat162*)(Ch + (size_t)r1 * N + col) = __halves2bfloat162(h10, h11);
                *(__nv_bfloat162*)(Cl + (size_t)r1 * N + col) = __halves2bfloat162(l10, l11);
            }
        }
    }
}

// ---------------- flash attention (causal, scale = 1/32) -> bf16 hi/lo ----------------
__global__ void __launch_bounds__(256)
attn_kernel(const float* __restrict__ qkv,
            __nv_bfloat16* __restrict__ outh, __nv_bfloat16* __restrict__ outl) {
    extern __shared__ float sm[];
    float* Qs = sm;                  // [64][64]
    float* Ks = Qs + 64 * 64;        // [64][65]
    float* Vs = Ks + 64 * 65;        // [64][64]
    float* Ps = Vs + 64 * 64;        // [8][64]

    int bh = blockIdx.y;
    int b = bh / Hn, h = bh % Hn;
    int q0 = blockIdx.x * 64;
    int tid = threadIdx.x;
    int w = tid >> 5, l = tid & 31;

    const size_t rs = QKVN;
    const float* Qg = qkv + ((size_t)b * Tn + q0) * rs + h * HDn;
    const float* Kg = qkv + ((size_t)b * Tn) * rs + En + h * HDn;
    const float* Vg = Kg + En;

#pragma unroll
    for (int it = 0; it < 16; it++) {
        int idx = it * 256 + tid;
        int r = idx >> 6, d = idx & 63;
        Qs[r * 64 + d] = Qg[(size_t)r * rs + d];
    }

    float m[8], ssum[8], o0[8], o1[8];
#pragma unroll
    for (int r = 0; r < 8; r++) { m[r] = -1e30f; ssum[r] = 0.f; o0[r] = 0.f; o1[r] = 0.f; }

    for (int j0 = 0; j0 <= q0; j0 += 64) {
        __syncthreads();
#pragma unroll
        for (int it = 0; it < 16; it++) {
            int idx = it * 256 + tid;
            int r = idx >> 6, d = idx & 63;
            Ks[r * 65 + d] = Kg[((size_t)j0 + r) * rs + d];
            Vs[r * 64 + d] = Vg[((size_t)j0 + r) * rs + d];
        }
        __syncthreads();
        bool lastChunk = (j0 == q0);

#pragma unroll
        for (int r = 0; r < 8; r++) {
            int qg = q0 + w * 8 + r;
            const float* qrow = &Qs[(w * 8 + r) * 64];
            float s0 = 0.f, s1 = 0.f;
#pragma unroll 16
            for (int d = 0; d < 64; d++) {
                float qd = qrow[d];
                s0 += qd * Ks[l * 65 + d];
                s1 += qd * Ks[(l + 32) * 65 + d];
            }
            s0 *= 0.03125f; s1 *= 0.03125f;
            if (lastChunk) {
                if (j0 + l      > qg) s0 = -1e30f;
                if (j0 + l + 32 > qg) s1 = -1e30f;
            }
            float mc = fmaxf(s0, s1);
#pragma unroll
            for (int o = 16; o; o >>= 1) mc = fmaxf(mc, __shfl_xor_sync(0xFFFFFFFFu, mc, o));
            float mn = fmaxf(m[r], mc);
            float alpha = __expf(m[r] - mn);
            float p0 = __expf(s0 - mn), p1 = __expf(s1 - mn);
            float ps = p0 + p1;
#pragma unroll
            for (int o = 16; o; o >>= 1) ps += __shfl_xor_sync(0xFFFFFFFFu, ps, o);
            ssum[r] = ssum[r] * alpha + ps;
            m[r] = mn;
            o0[r] *= alpha; o1[r] *= alpha;
            Ps[w * 64 + l]      = p0;
            Ps[w * 64 + l + 32] = p1;
            __syncwarp();
            float a0 = 0.f, a1 = 0.f;
#pragma unroll 16
            for (int kk = 0; kk < 64; kk++) {
                float p = Ps[w * 64 + kk];
                a0 += p * Vs[kk * 64 + l];
                a1 += p * Vs[kk * 64 + l + 32];
            }
            o0[r] += a0; o1[r] += a1;
            __syncwarp();
        }
    }

#pragma unroll
    for (int r = 0; r < 8; r++) {
        int qg = q0 + w * 8 + r;
        float inv = 1.0f / ssum[r];
        size_t base = ((size_t)b * Tn + qg) * En + h * HDn;
        float v0 = o0[r] * inv, v1 = o1[r] * inv;
        __nv_bfloat16 h0, l0_, h1, l1_;
        split_bf16(v0, h0, l0_);
        split_bf16(v1, h1, l1_);
        outh[base + l]      = h0;  outl[base + l]      = l0_;
        outh[base + l + 32] = h1;  outl[base + l + 32] = l1_;
    }
}

// ---------------- launch ----------------
extern "C" void kernel_launch(void* const* d_in, const int* in_sizes, int n_in,
                              void* d_out, int out_size) {
    const float* x     = (const float*)d_in[0];
    const float* Wq    = (const float*)d_in[1];
    const float* Wk    = (const float*)d_in[2];
    const float* Wv    = (const float*)d_in[3];
    const float* Wproj = (const float*)d_in[4];
    const float* bproj = (const float*)d_in[5];
    const float* W1    = (const float*)d_in[6];
    const float* b1    = (const float*)d_in[7];
    const float* W2    = (const float*)d_in[8];
    const float* b2    = (const float*)d_in[9];
    const float* g1    = (const float*)d_in[10];
    const float* be1   = (const float*)d_in[11];
    const float* g2    = (const float*)d_in[12];
    const float* be2   = (const float*)d_in[13];
    float* out = (float*)d_out;

    float *qkv, *x2;
    __nv_bfloat16 *h1h, *h1l, *h2h, *h2l, *aoh, *aol, *midh, *midl;
    __nv_bfloat16 *wqkvh, *wqkvl, *wph, *wpl, *w1h, *w1l, *w2h, *w2l;
    cudaGetSymbolAddress((void**)&qkv,   g_qkv);
    cudaGetSymbolAddress((void**)&x2,    g_x2);
    cudaGetSymbolAddress((void**)&h1h,   g_h1h);  cudaGetSymbolAddress((void**)&h1l, g_h1l);
    cudaGetSymbolAddress((void**)&h2h,   g_h2h);  cudaGetSymbolAddress((void**)&h2l, g_h2l);
    cudaGetSymbolAddress((void**)&aoh,   g_aoh);  cudaGetSymbolAddress((void**)&aol, g_aol);
    cudaGetSymbolAddress((void**)&midh,  g_midh); cudaGetSymbolAddress((void**)&midl, g_midl);
    cudaGetSymbolAddress((void**)&wqkvh, g_wqkvh); cudaGetSymbolAddress((void**)&wqkvl, g_wqkvl);
    cudaGetSymbolAddress((void**)&wph,   g_wph);  cudaGetSymbolAddress((void**)&wpl, g_wpl);
    cudaGetSymbolAddress((void**)&w1h,   g_w1h);  cudaGetSymbolAddress((void**)&w1l, g_w1l);
    cudaGetSymbolAddress((void**)&w2h,   g_w2h);  cudaGetSymbolAddress((void**)&w2l, g_w2l);

    const int GEMM_SMEM = 2 * 32768;   // 64KB
    cudaFuncSetAttribute(mma_gemm<0>, cudaFuncAttributeMaxDynamicSharedMemorySize, GEMM_SMEM);
    cudaFuncSetAttribute(mma_gemm<1>, cudaFuncAttributeMaxDynamicSharedMemorySize, GEMM_SMEM);
    cudaFuncSetAttribute(mma_gemm<2>, cudaFuncAttributeMaxDynamicSharedMemorySize, GEMM_SMEM);
    const int ATTN_SMEM = (64 * 64 + 64 * 65 + 64 * 64 + 8 * 64) * 4;
    cudaFuncSetAttribute(attn_kernel, cudaFuncAttributeMaxDynamicSharedMemorySize, ATTN_SMEM);

    // weight packs (hi/lo bf16, [N,K] layout)
    pack_qkv_kernel<<<(QKVN * En + 255) / 256, 256>>>(Wq, Wk, Wv, wqkvh, wqkvl);
    pack_t_kernel<<<(En * En + 255) / 256, 256>>>(Wproj, wph, wpl, En, En);
    pack_t_kernel<<<(En * FFn + 255) / 256, 256>>>(W1, w1h, w1l, En, FFn);
    pack_t_kernel<<<(FFn * En + 255) / 256, 256>>>(W2, w2h, w2l, FFn, En);

    // LN1 -> h1 hi/lo
    ln_kernel<<<Mn, 256>>>(x, g1, be1, h1h, h1l);
    // QKV GEMM: [4096,1024] x [3072,1024]^T -> qkv fp32
    mma_gemm<0><<<dim3(QKVN / 128, Mn / 128), 256, GEMM_SMEM>>>(
        h1h, h1l, wqkvh, wqkvl, Mn, QKVN, En, nullptr, nullptr, qkv, nullptr, nullptr);
    // attention -> attno hi/lo
    attn_kernel<<<dim3(Tn / 64, Bn * Hn), 256, ATTN_SMEM>>>(qkv, aoh, aol);
    // proj + bias + residual(x) -> x2 fp32
    mma_gemm<1><<<dim3(En / 128, Mn / 128), 256, GEMM_SMEM>>>(
        aoh, aol, wph, wpl, Mn, En, En, bproj, x, x2, nullptr, nullptr);
    // LN2 -> h2 hi/lo
    ln_kernel<<<Mn, 256>>>(x2, g2, be2, h2h, h2l);
    // FFN1: relu(h2 @ W1 + b1) -> mid hi/lo
    mma_gemm<2><<<dim3(FFn / 128, Mn / 128), 256, GEMM_SMEM>>>(
        h2h, h2l, w1h, w1l, Mn, FFn, En, b1, nullptr, nullptr, midh, midl);
    // FFN2: x2 + mid @ W2 + b2 -> out fp32
    mma_gemm<1><<<dim3(En / 128, Mn / 128), 256, GEMM_SMEM>>>(
        midh, midl, w2h, w2l, Mn, En, FFn, b2, x2, out, nullptr, nullptr);
}

// round 4
// speedup vs baseline: 3.7973x; 2.2383x over previous
#include <cuda_runtime.h>
#include <cuda_bf16.h>
#include <cstdint>
#include <cstddef>

#define Bn 2
#define Tn 2048
#define En 1024
#define Hn 16
#define HDn 64
#define FFn 4096
#define Mn (Bn*Tn)          // 4096
#define QKVN (3*En)         // 3072

// ---------------- scratch (device globals) ----------------
__device__ float g_x2[(size_t)Mn*En];                          // 16 MB fp32
__device__ __nv_bfloat16 g_qkvh[(size_t)Mn*QKVN], g_qkvl[(size_t)Mn*QKVN];
__device__ __nv_bfloat16 g_h1h[(size_t)Mn*En],  g_h1l[(size_t)Mn*En];
__device__ __nv_bfloat16 g_h2h[(size_t)Mn*En],  g_h2l[(size_t)Mn*En];
__device__ __nv_bfloat16 g_aoh[(size_t)Mn*En],  g_aol[(size_t)Mn*En];
__device__ __nv_bfloat16 g_midh[(size_t)Mn*FFn], g_midl[(size_t)Mn*FFn];
__device__ __nv_bfloat16 g_wqkvh[(size_t)QKVN*En], g_wqkvl[(size_t)QKVN*En];
__device__ __nv_bfloat16 g_wph[(size_t)En*En],   g_wpl[(size_t)En*En];
__device__ __nv_bfloat16 g_w1h[(size_t)FFn*En],  g_w1l[(size_t)FFn*En];
__device__ __nv_bfloat16 g_w2h[(size_t)En*FFn],  g_w2l[(size_t)En*FFn];

// ---------------- helpers ----------------
__device__ __forceinline__ void split_bf16(float v, __nv_bfloat16& h, __nv_bfloat16& l) {
    h = __float2bfloat16(v);
    l = __float2bfloat16(v - __bfloat162float(h));
}

__device__ __forceinline__ void split_pack(float a, float b, uint32_t& hi, uint32_t& lo) {
    __nv_bfloat16 ha = __float2bfloat16(a), hb = __float2bfloat16(b);
    __nv_bfloat16 la = __float2bfloat16(a - __bfloat162float(ha));
    __nv_bfloat16 lb = __float2bfloat16(b - __bfloat162float(hb));
    __nv_bfloat162 H = __halves2bfloat162(ha, hb), L = __halves2bfloat162(la, lb);
    hi = *reinterpret_cast<uint32_t*>(&H);
    lo = *reinterpret_cast<uint32_t*>(&L);
}

__device__ __forceinline__ uint32_t s2u(const void* p) {
    uint32_t a;
    asm("{ .reg .u64 t; cvta.to.shared.u64 t, %1; cvt.u32.u64 %0, t; }" : "=r"(a) : "l"(p));
    return a;
}

__device__ __forceinline__ void cp16(uint32_t s, const void* g) {
    asm volatile("cp.async.cg.shared.global [%0], [%1], 16;" :: "r"(s), "l"(g));
}
#define CP_COMMIT() asm volatile("cp.async.commit_group;")
#define CP_WAIT(N)  asm volatile("cp.async.wait_group %0;" :: "n"(N))

#define LDM4(r, addr) \
    asm volatile("ldmatrix.sync.aligned.m8n8.x4.shared.b16 {%0,%1,%2,%3}, [%4];" \
        : "=r"((r)[0]), "=r"((r)[1]), "=r"((r)[2]), "=r"((r)[3]) : "r"(addr))

#define LDM4T(r, addr) \
    asm volatile("ldmatrix.sync.aligned.m8n8.x4.trans.shared.b16 {%0,%1,%2,%3}, [%4];" \
        : "=r"((r)[0]), "=r"((r)[1]), "=r"((r)[2]), "=r"((r)[3]) : "r"(addr))

#define MMA_BF16(d, a, b0, b1) \
    asm volatile("mma.sync.aligned.m16n8k16.row.col.f32.bf16.bf16.f32 " \
        "{%0,%1,%2,%3}, {%4,%5,%6,%7}, {%8,%9}, {%0,%1,%2,%3};" \
        : "+f"((d)[0]), "+f"((d)[1]), "+f"((d)[2]), "+f"((d)[3]) \
        : "r"((a)[0]), "r"((a)[1]), "r"((a)[2]), "r"((a)[3]), "r"(b0), "r"(b1))

// fast exp2 for t <= 0 (degree-6 Taylor of 2^f, rel err ~1.5e-5), FMA pipe only
__device__ __forceinline__ float exp2f_fast(float t) {
    t = fmaxf(t, -126.0f);
    float fi = floorf(t);
    float f = t - fi;
    float p = 1.5403530e-4f;
    p = fmaf(p, f, 1.3333558e-3f);
    p = fmaf(p, f, 9.6181291e-3f);
    p = fmaf(p, f, 5.5504109e-2f);
    p = fmaf(p, f, 2.4022651e-1f);
    p = fmaf(p, f, 6.9314718e-1f);
    p = fmaf(p, f, 1.0f);
    return __int_as_float(__float_as_int(p) + ((int)fi << 23));
}

// ---------------- weight pack kernels ----------------
__global__ void pack_qkv_kernel(const float* __restrict__ Wq, const float* __restrict__ Wk,
                                const float* __restrict__ Wv,
                                __nv_bfloat16* __restrict__ oh, __nv_bfloat16* __restrict__ ol) {
    int i = blockIdx.x * 256 + threadIdx.x;          // over QKVN*En
    if (i >= QKVN * En) return;
    int n = i / En, k = i % En;
    int sel = n >> 10;                // 0=q 1=k 2=v
    int hc = n & 1023;
    int h = hc >> 6, e = hc & 63;
    const float* W = (sel == 0) ? Wq : (sel == 1) ? Wk : Wv;
    float v = W[((size_t)h * En + k) * HDn + e];
    __nv_bfloat16 hi, lo; split_bf16(v, hi, lo);
    oh[i] = hi; ol[i] = lo;
}

// transpose + split: In [K, N] -> out [N, K]
__global__ void pack_t_kernel(const float* __restrict__ In,
                              __nv_bfloat16* __restrict__ oh, __nv_bfloat16* __restrict__ ol,
                              int K, int N) {
    int i = blockIdx.x * 256 + threadIdx.x;          // over N*K
    if (i >= N * K) return;
    int n = i / K, k = i % K;
    float v = In[(size_t)k * N + n];
    __nv_bfloat16 hi, lo; split_bf16(v, hi, lo);
    oh[i] = hi; ol[i] = lo;
}

// ---------------- LayerNorm: fp32 in -> bf16 hi/lo out ----------------
__global__ void ln_kernel(const float* __restrict__ x, const float* __restrict__ g,
                          const float* __restrict__ b,
                          __nv_bfloat16* __restrict__ oh, __nv_bfloat16* __restrict__ ol) {
    int row = blockIdx.x;
    const float* xr = x + (size_t)row * En;
    float v[4];
    float s = 0.f, sq = 0.f;
#pragma unroll
    for (int i = 0; i < 4; i++) {
        v[i] = xr[threadIdx.x + i * 256];
        s += v[i]; sq += v[i] * v[i];
    }
    __shared__ float red[18];
#pragma unroll
    for (int o = 16; o; o >>= 1) {
        s  += __shfl_xor_sync(0xFFFFFFFFu, s,  o);
        sq += __shfl_xor_sync(0xFFFFFFFFu, sq, o);
    }
    int w = threadIdx.x >> 5, l = threadIdx.x & 31;
    if (l == 0) { red[w] = s; red[8 + w] = sq; }
    __syncthreads();
    if (threadIdx.x == 0) {
        float ts = 0.f, tq = 0.f;
#pragma unroll
        for (int i = 0; i < 8; i++) { ts += red[i]; tq += red[8 + i]; }
        red[16] = ts; red[17] = tq;
    }
    __syncthreads();
    float mean = red[16] * (1.f / En);
    float var  = red[17] * (1.f / En) - mean * mean;
    float rstd = rsqrtf(var + 1e-5f);
#pragma unroll
    for (int i = 0; i < 4; i++) {
        int c = threadIdx.x + i * 256;
        float y = (v[i] - mean) * rstd * g[c] + b[c];
        __nv_bfloat16 hi, lo; split_bf16(y, hi, lo);
        oh[(size_t)row * En + c] = hi;
        ol[(size_t)row * En + c] = lo;
    }
}

// ---------------- mma.sync GEMM: C[M,N] = (Ah+Al)[M,K] @ (Bh+Bl)^T ([N,K]) ----------------
// EPI: 1 = fp32 out + bias + residual; 2 = relu(+bias) -> bf16 hi/lo; 3 = bf16 hi/lo (no bias)
template<int EPI>
__global__ void __launch_bounds__(256, 1)
mma_gemm(const __nv_bfloat16* __restrict__ Ah, const __nv_bfloat16* __restrict__ Al,
         const __nv_bfloat16* __restrict__ Bh, const __nv_bfloat16* __restrict__ Bl,
         int M, int N, int K,
         const float* __restrict__ bias, const float* __restrict__ res,
         float* __restrict__ Cf,
         __nv_bfloat16* __restrict__ Ch, __nv_bfloat16* __restrict__ Cl) {
    extern __shared__ __align__(1024) char smem[];
    const uint32_t su = s2u(smem);
    const int tid = threadIdx.x;
    const int lane = tid & 31, wid = tid >> 5;
    const int warp_m = wid & 1, warp_n = wid >> 1;
    const int brow = blockIdx.y * 128, bcol = blockIdx.x * 128;
    const int S = K >> 5;      // stages of BK=32

    const int mat = lane >> 3, rowm = lane & 7;
    const int c16bA = mat >> 1;
    const int c16bB = mat & 1;
    uint32_t mrow64[4], swmA[4];
#pragma unroll
    for (int mi = 0; mi < 4; mi++) {
        int m = warp_m * 64 + mi * 16 + (mat & 1) * 8 + rowm;
        mrow64[mi] = (uint32_t)(m * 64);
        swmA[mi] = (uint32_t)(((m >> 1) & 7) << 4);
    }
    uint32_t nrow64[2], swmB[2];
#pragma unroll
    for (int nj = 0; nj < 2; nj++) {
        int n = warp_n * 32 + nj * 16 + (mat >> 1) * 8 + rowm;
        nrow64[nj] = (uint32_t)(n * 64);
        swmB[nj] = (uint32_t)(((n >> 1) & 7) << 4);
    }

    float acc[4][4][4];
#pragma unroll
    for (int mi = 0; mi < 4; mi++)
#pragma unroll
        for (int j = 0; j < 4; j++)
#pragma unroll
            for (int r = 0; r < 4; r++) acc[mi][j][r] = 0.f;

    auto load_stage = [&](int s, int buf) {
        const int k0 = s * 32;
        const uint32_t sb = su + (uint32_t)buf * 32768;
#pragma unroll
        for (int i = 0; i < 2; i++) {
            int idx = tid + i * 256;          // 0..511
            int r = idx >> 2, c = idx & 3;
            uint32_t o = (uint32_t)(r * 64 + c * 16);
            uint32_t sw = o ^ (((o >> 7) & 7) << 4);
            size_t ao = (size_t)(brow + r) * K + k0 + c * 8;
            size_t bo = (size_t)(bcol + r) * K + k0 + c * 8;
            cp16(sb + sw,         Ah + ao);
            cp16(sb + 8192 + sw,  Al + ao);
            cp16(sb + 16384 + sw, Bh + bo);
            cp16(sb + 24576 + sw, Bl + bo);
        }
    };

    load_stage(0, 0);
    CP_COMMIT();

    for (int s = 0; s < S; s++) {
        if (s + 1 < S) { load_stage(s + 1, (s + 1) & 1); CP_COMMIT(); CP_WAIT(1); }
        else           { CP_WAIT(0); }
        __syncthreads();

        const uint32_t sb = su + (uint32_t)(s & 1) * 32768;
#pragma unroll
        for (int kk = 0; kk < 2; kk++) {
            uint32_t ah[4][4], al[4][4];
            const int cA = kk * 2 + c16bA;
#pragma unroll
            for (int mi = 0; mi < 4; mi++) {
                uint32_t oa = (mrow64[mi] + (uint32_t)(cA * 16)) ^ swmA[mi];
                LDM4(ah[mi], sb + oa);
                LDM4(al[mi], sb + 8192 + oa);
            }
            uint32_t bh[2][4], bl[2][4];
            const int cB = kk * 2 + c16bB;
#pragma unroll
            for (int nj = 0; nj < 2; nj++) {
                uint32_t ob = (nrow64[nj] + (uint32_t)(cB * 16)) ^ swmB[nj];
                LDM4(bh[nj], sb + 16384 + ob);
                LDM4(bl[nj], sb + 24576 + ob);
            }
#pragma unroll
            for (int mi = 0; mi < 4; mi++) {
#pragma unroll
                for (int j = 0; j < 4; j++) {
                    const int nj = j >> 1, rb = (j & 1) * 2;
                    MMA_BF16(acc[mi][j], ah[mi], bh[nj][rb], bh[nj][rb + 1]);
                    MMA_BF16(acc[mi][j], ah[mi], bl[nj][rb], bl[nj][rb + 1]);
                    MMA_BF16(acc[mi][j], al[mi], bh[nj][rb], bh[nj][rb + 1]);
                }
            }
        }
        __syncthreads();
    }

    // ---------------- epilogue ----------------
    const int rowbase = brow + warp_m * 64 + (lane >> 2);
    const int colbase = bcol + warp_n * 32 + (lane & 3) * 2;
#pragma unroll
    for (int mi = 0; mi < 4; mi++) {
#pragma unroll
        for (int j = 0; j < 4; j++) {
            int col = colbase + j * 8;
            int r0 = rowbase + mi * 16;
            int r1 = r0 + 8;
            float v00 = acc[mi][j][0], v01 = acc[mi][j][1];
            float v10 = acc[mi][j][2], v11 = acc[mi][j][3];
            if (EPI == 1) {
                float b0 = bias[col], b1 = bias[col + 1];
                const float2 rr0 = *(const float2*)(res + (size_t)r0 * N + col);
                const float2 rr1 = *(const float2*)(res + (size_t)r1 * N + col);
                *(float2*)(Cf + (size_t)r0 * N + col) = make_float2(v00 + b0 + rr0.x, v01 + b1 + rr0.y);
                *(float2*)(Cf + (size_t)r1 * N + col) = make_float2(v10 + b0 + rr1.x, v11 + b1 + rr1.y);
            } else if (EPI == 2) {
                float b0 = bias[col], b1 = bias[col + 1];
                float w00 = fmaxf(v00 + b0, 0.f), w01 = fmaxf(v01 + b1, 0.f);
                float w10 = fmaxf(v10 + b0, 0.f), w11 = fmaxf(v11 + b1, 0.f);
                uint32_t h0, l0, h1, l1;
                split_pack(w00, w01, h0, l0);
                split_pack(w10, w11, h1, l1);
                *(uint32_t*)(Ch + (size_t)r0 * N + col) = h0;
                *(uint32_t*)(Cl + (size_t)r0 * N + col) = l0;
                *(uint32_t*)(Ch + (size_t)r1 * N + col) = h1;
                *(uint32_t*)(Cl + (size_t)r1 * N + col) = l1;
            } else {  // EPI == 3: raw bf16 hi/lo
                uint32_t h0, l0, h1, l1;
                split_pack(v00, v01, h0, l0);
                split_pack(v10, v11, h1, l1);
                *(uint32_t*)(Ch + (size_t)r0 * N + col) = h0;
                *(uint32_t*)(Cl + (size_t)r0 * N + col) = l0;
                *(uint32_t*)(Ch + (size_t)r1 * N + col) = h1;
                *(uint32_t*)(Cl + (size_t)r1 * N + col) = l1;
            }
        }
    }
}

// ---------------- mma.sync flash attention (causal, scale = 1/32) ----------------
// Q tile 128 x HD64 per CTA; 8 warps x 16 query rows; key chunks of 64,
// double-buffered cp.async. 3-term split-precision QK and PV. exp via FMA poly.
__global__ void __launch_bounds__(256, 1)
attn_mma(const __nv_bfloat16* __restrict__ qkvh, const __nv_bfloat16* __restrict__ qkvl,
         __nv_bfloat16* __restrict__ outh, __nv_bfloat16* __restrict__ outl) {
    extern __shared__ __align__(1024) char smem[];
    const uint32_t su = s2u(smem);
    const int tid = threadIdx.x, lane = tid & 31, w = tid >> 5;
    const int mat = lane >> 3, rowm = lane & 7;
    const uint32_t swx = (uint32_t)rowm << 4;

    const int tile = (Tn / 128 - 1) - blockIdx.x;   // biggest tiles first
    const int bh = blockIdx.y, b = bh >> 4, h = bh & 15;
    const int q0 = tile * 128;
    const int nch = 2 * (tile + 1);
    const size_t RS = QKVN;

    const __nv_bfloat16* Qh  = qkvh + ((size_t)b * Tn + q0) * RS + h * HDn;
    const __nv_bfloat16* Ql_ = qkvl + ((size_t)b * Tn + q0) * RS + h * HDn;
    const __nv_bfloat16* Kh  = qkvh + (size_t)b * Tn * RS + En + h * HDn;
    const __nv_bfloat16* Kl  = qkvl + (size_t)b * Tn * RS + En + h * HDn;
    const __nv_bfloat16* Vh  = qkvh + (size_t)b * Tn * RS + 2 * En + h * HDn;
    const __nv_bfloat16* Vl  = qkvl + (size_t)b * Tn * RS + 2 * En + h * HDn;

    // Q tile (128 x 64 bf16 hi+lo) -> smem [0, 32KB)
#pragma unroll
    for (int i = 0; i < 8; i++) {
        int idx = tid + i * 256;      // 0..2047
        int tns = idx >> 10;
        int r = (idx >> 3) & 127;
        int c = idx & 7;
        uint32_t o = (uint32_t)(r * 128 + c * 16);
        uint32_t sw = o ^ (uint32_t)((r & 7) << 4);
        const __nv_bfloat16* src = (tns ? Ql_ : Qh) + (size_t)r * RS + c * 8;
        cp16(su + (uint32_t)tns * 16384 + sw, src);
    }
    CP_COMMIT();

    auto loadKV = [&](int j, int buf) {
        const int j0 = j * 64;
        const uint32_t sb = su + 32768 + (uint32_t)buf * 32768;
#pragma unroll
        for (int i = 0; i < 8; i++) {
            int idx = tid + i * 256;   // 0..2047
            int tns = idx >> 9;        // 0..3: Kh,Kl,Vh,Vl
            int r = (idx >> 3) & 63;
            int c = idx & 7;
            uint32_t o = (uint32_t)(r * 128 + c * 16);
            uint32_t sw = o ^ (uint32_t)((r & 7) << 4);
            size_t go = (size_t)(j0 + r) * RS + c * 8;
            const __nv_bfloat16* src = (tns == 0) ? Kh + go : (tns == 1) ? Kl + go
                                     : (tns == 2) ? Vh + go : Vl + go;
            cp16(sb + (uint32_t)tns * 8192 + sw, src);
        }
    };
    loadKV(0, 0);
    CP_COMMIT();
    CP_WAIT(1);            // Q done
    __syncthreads();

    // Q fragments (persist): 4 k-steps x 4 regs, hi+lo
    uint32_t qfh[4][4], qfl[4][4];
    {
        int m = w * 16 + (mat & 1) * 8 + rowm;
#pragma unroll
        for (int s = 0; s < 4; s++) {
            uint32_t o = ((uint32_t)(m * 128 + s * 32 + (mat >> 1) * 16)) ^ swx;
            LDM4(qfh[s], su + o);
            LDM4(qfl[s], su + 16384 + o);
        }
    }

    float O[8][4];
#pragma unroll
    for (int a = 0; a < 8; a++)
#pragma unroll
        for (int r = 0; r < 4; r++) O[a][r] = 0.f;
    float m0 = -1e30f, m1 = -1e30f, l0 = 0.f, l1 = 0.f;

    const int rmin = q0 + w * 16;
    const int r0g = rmin + (lane >> 2), r1g = r0g + 8;
    const float SCL = 0.04508422f;   // log2(e) / 32

    for (int j = 0; j < nch; j++) {
        if (j + 1 < nch) { loadKV(j + 1, (j + 1) & 1); CP_COMMIT(); CP_WAIT(1); }
        else             { CP_WAIT(0); }
        __syncthreads();

        const int j0 = j * 64;
        if (j0 <= rmin + 15) {
            const uint32_t sb = su + 32768 + (uint32_t)(j & 1) * 32768;

            // ---- S = Q K^T (3-term split) ----
            float S[8][4];
#pragma unroll
            for (int jt = 0; jt < 8; jt++)
#pragma unroll
                for (int r = 0; r < 4; r++) S[jt][r] = 0.f;
#pragma unroll
            for (int s = 0; s < 4; s++) {
                uint32_t kh4[4][4], kl4[4][4];
#pragma unroll
                for (int nb = 0; nb < 4; nb++) {
                    int n = nb * 16 + (mat >> 1) * 8 + rowm;
                    uint32_t o = ((uint32_t)(n * 128 + s * 32 + (mat & 1) * 16)) ^ swx;
                    LDM4(kh4[nb], sb + o);
                    LDM4(kl4[nb], sb + 8192 + o);
                }
#pragma unroll
                for (int nb = 0; nb < 4; nb++) {
#pragma unroll
                    for (int hf = 0; hf < 2; hf++) {
                        int jt = nb * 2 + hf;
                        MMA_BF16(S[jt], qfh[s], kh4[nb][hf * 2], kh4[nb][hf * 2 + 1]);
                        MMA_BF16(S[jt], qfh[s], kl4[nb][hf * 2], kl4[nb][hf * 2 + 1]);
                        MMA_BF16(S[jt], qfl[s], kh4[nb][hf * 2], kh4[nb][hf * 2 + 1]);
                    }
                }
            }

            // ---- scale (to log2 domain) + causal mask ----
#pragma unroll
            for (int jt = 0; jt < 8; jt++) {
                S[jt][0] *= SCL; S[jt][1] *= SCL; S[jt][2] *= SCL; S[jt][3] *= SCL;
            }
            if (j0 + 63 > rmin) {
#pragma unroll
                for (int jt = 0; jt < 8; jt++) {
                    int c0 = j0 + jt * 8 + 2 * (lane & 3);
                    if (c0 > r0g)     S[jt][0] = -1e30f;
                    if (c0 + 1 > r0g) S[jt][1] = -1e30f;
                    if (c0 > r1g)     S[jt][2] = -1e30f;
                    if (c0 + 1 > r1g) S[jt][3] = -1e30f;
                }
            }

            // ---- online softmax (base-2) ----
            float mx0 = -1e30f, mx1 = -1e30f;
#pragma unroll
            for (int jt = 0; jt < 8; jt++) {
                mx0 = fmaxf(mx0, fmaxf(S[jt][0], S[jt][1]));
                mx1 = fmaxf(mx1, fmaxf(S[jt][2], S[jt][3]));
            }
            mx0 = fmaxf(mx0, __shfl_xor_sync(0xFFFFFFFFu, mx0, 1));
            mx0 = fmaxf(mx0, __shfl_xor_sync(0xFFFFFFFFu, mx0, 2));
            mx1 = fmaxf(mx1, __shfl_xor_sync(0xFFFFFFFFu, mx1, 1));
            mx1 = fmaxf(mx1, __shfl_xor_sync(0xFFFFFFFFu, mx1, 2));
            float mn0 = fmaxf(m0, mx0), mn1 = fmaxf(m1, mx1);
            float al0 = exp2f_fast(m0 - mn0), al1 = exp2f_fast(m1 - mn1);
            m0 = mn0; m1 = mn1;
            float s0 = 0.f, s1 = 0.f;
#pragma unroll
            for (int jt = 0; jt < 8; jt++) {
                float p0 = exp2f_fast(S[jt][0] - mn0); S[jt][0] = p0;
                float p1 = exp2f_fast(S[jt][1] - mn0); S[jt][1] = p1;
                float p2 = exp2f_fast(S[jt][2] - mn1); S[jt][2] = p2;
                float p3 = exp2f_fast(S[jt][3] - mn1); S[jt][3] = p3;
                s0 += p0 + p1; s1 += p2 + p3;
            }
            s0 += __shfl_xor_sync(0xFFFFFFFFu, s0, 1);
            s0 += __shfl_xor_sync(0xFFFFFFFFu, s0, 2);
            s1 += __shfl_xor_sync(0xFFFFFFFFu, s1, 1);
            s1 += __shfl_xor_sync(0xFFFFFFFFu, s1, 2);
            l0 = l0 * al0 + s0;
            l1 = l1 * al1 + s1;
#pragma unroll
            for (int dt = 0; dt < 8; dt++) {
                O[dt][0] *= al0; O[dt][1] *= al0; O[dt][2] *= al1; O[dt][3] *= al1;
            }

            // ---- O += P V (3-term split) ----
#pragma unroll
            for (int s = 0; s < 4; s++) {
                const int t0 = 2 * s, t1 = 2 * s + 1;
                uint32_t ph[4], pl[4];
                split_pack(S[t0][0], S[t0][1], ph[0], pl[0]);
                split_pack(S[t0][2], S[t0][3], ph[1], pl[1]);
                split_pack(S[t1][0], S[t1][1], ph[2], pl[2]);
                split_pack(S[t1][2], S[t1][3], ph[3], pl[3]);
                uint32_t vh4[4][4], vl4[4][4];
#pragma unroll
                for (int nb = 0; nb < 4; nb++) {
                    int kr = s * 16 + (mat & 1) * 8 + rowm;
                    uint32_t o = ((uint32_t)(kr * 128 + (nb * 16 + (mat >> 1) * 8) * 2)) ^ swx;
                    LDM4T(vh4[nb], sb + 16384 + o);
                    LDM4T(vl4[nb], sb + 24576 + o);
                }
#pragma unroll
                for (int nb = 0; nb < 4; nb++) {
#pragma unroll
                    for (int hf = 0; hf < 2; hf++) {
                        int dt = nb * 2 + hf;
                        MMA_BF16(O[dt], ph, vh4[nb][hf * 2], vh4[nb][hf * 2 + 1]);
                        MMA_BF16(O[dt], ph, vl4[nb][hf * 2], vl4[nb][hf * 2 + 1]);
                        MMA_BF16(O[dt], pl, vh4[nb][hf * 2], vh4[nb][hf * 2 + 1]);
                    }
                }
            }
        }
        __syncthreads();
    }

    // ---- normalize + store bf16 hi/lo ----
    float inv0 = 1.f / l0, inv1 = 1.f / l1;
#pragma unroll
    for (int dt = 0; dt < 8; dt++) {
        int col = h * 64 + dt * 8 + 2 * (lane & 3);
        size_t o0 = ((size_t)b * Tn + r0g) * En + col;
        size_t o1 = ((size_t)b * Tn + r1g) * En + col;
        uint32_t hA, lA, hB, lB;
        split_pack(O[dt][0] * inv0, O[dt][1] * inv0, hA, lA);
        split_pack(O[dt][2] * inv1, O[dt][3] * inv1, hB, lB);
        *(uint32_t*)(outh + o0) = hA; *(uint32_t*)(outl + o0) = lA;
        *(uint32_t*)(outh + o1) = hB; *(uint32_t*)(outl + o1) = lB;
    }
}

// ---------------- launch ----------------
extern "C" void kernel_launch(void* const* d_in, const int* in_sizes, int n_in,
                              void* d_out, int out_size) {
    const float* x     = (const float*)d_in[0];
    const float* Wq    = (const float*)d_in[1];
    const float* Wk    = (const float*)d_in[2];
    const float* Wv    = (const float*)d_in[3];
    const float* Wproj = (const float*)d_in[4];
    const float* bproj = (const float*)d_in[5];
    const float* W1    = (const float*)d_in[6];
    const float* b1    = (const float*)d_in[7];
    const float* W2    = (const float*)d_in[8];
    const float* b2    = (const float*)d_in[9];
    const float* g1    = (const float*)d_in[10];
    const float* be1   = (const float*)d_in[11];
    const float* g2    = (const float*)d_in[12];
    const float* be2   = (const float*)d_in[13];
    float* out = (float*)d_out;

    float *x2;
    __nv_bfloat16 *qkvh, *qkvl, *h1h, *h1l, *h2h, *h2l, *aoh, *aol, *midh, *midl;
    __nv_bfloat16 *wqkvh, *wqkvl, *wph, *wpl, *w1h, *w1l, *w2h, *w2l;
    cudaGetSymbolAddress((void**)&x2,    g_x2);
    cudaGetSymbolAddress((void**)&qkvh,  g_qkvh);  cudaGetSymbolAddress((void**)&qkvl, g_qkvl);
    cudaGetSymbolAddress((void**)&h1h,   g_h1h);   cudaGetSymbolAddress((void**)&h1l,  g_h1l);
    cudaGetSymbolAddress((void**)&h2h,   g_h2h);   cudaGetSymbolAddress((void**)&h2l,  g_h2l);
    cudaGetSymbolAddress((void**)&aoh,   g_aoh);   cudaGetSymbolAddress((void**)&aol,  g_aol);
    cudaGetSymbolAddress((void**)&midh,  g_midh);  cudaGetSymbolAddress((void**)&midl, g_midl);
    cudaGetSymbolAddress((void**)&wqkvh, g_wqkvh); cudaGetSymbolAddress((void**)&wqkvl, g_wqkvl);
    cudaGetSymbolAddress((void**)&wph,   g_wph);   cudaGetSymbolAddress((void**)&wpl,  g_wpl);
    cudaGetSymbolAddress((void**)&w1h,   g_w1h);   cudaGetSymbolAddress((void**)&w1l,  g_w1l);
    cudaGetSymbolAddress((void**)&w2h,   g_w2h);   cudaGetSymbolAddress((void**)&w2l,  g_w2l);

    const int GEMM_SMEM = 2 * 32768;   // 64KB
    cudaFuncSetAttribute(mma_gemm<1>, cudaFuncAttributeMaxDynamicSharedMemorySize, GEMM_SMEM);
    cudaFuncSetAttribute(mma_gemm<2>, cudaFuncAttributeMaxDynamicSharedMemorySize, GEMM_SMEM);
    cudaFuncSetAttribute(mma_gemm<3>, cudaFuncAttributeMaxDynamicSharedMemorySize, GEMM_SMEM);
    const int ATTN_SMEM = 32768 + 2 * 32768;   // Q 32KB + KV double buffer 64KB
    cudaFuncSetAttribute(attn_mma, cudaFuncAttributeMaxDynamicSharedMemorySize, ATTN_SMEM);

    // weight packs (hi/lo bf16, [N,K] layout)
    pack_qkv_kernel<<<(QKVN * En + 255) / 256, 256>>>(Wq, Wk, Wv, wqkvh, wqkvl);
    pack_t_kernel<<<(En * En + 255) / 256, 256>>>(Wproj, wph, wpl, En, En);
    pack_t_kernel<<<(En * FFn + 255) / 256, 256>>>(W1, w1h, w1l, En, FFn);
    pack_t_kernel<<<(FFn * En + 255) / 256, 256>>>(W2, w2h, w2l, FFn, En);

    // LN1 -> h1 hi/lo
    ln_kernel<<<Mn, 256>>>(x, g1, be1, h1h, h1l);
    // QKV GEMM: -> qkv bf16 hi/lo
    mma_gemm<3><<<dim3(QKVN / 128, Mn / 128), 256, GEMM_SMEM>>>(
        h1h, h1l, wqkvh, wqkvl, Mn, QKVN, En, nullptr, nullptr, nullptr, qkvh, qkvl);
    // flash attention -> attno hi/lo
    attn_mma<<<dim3(Tn / 128, Bn * Hn), 256, ATTN_SMEM>>>(qkvh, qkvl, aoh, aol);
    // proj + bias + residual(x) -> x2 fp32
    mma_gemm<1><<<dim3(En / 128, Mn / 128), 256, GEMM_SMEM>>>(
        aoh, aol, wph, wpl, Mn, En, En, bproj, x, x2, nullptr, nullptr);
    // LN2 -> h2 hi/lo
    ln_kernel<<<Mn, 256>>>(x2, g2, be2, h2h, h2l);
    // FFN1: relu(h2 @ W1 + b1) -> mid hi/lo
    mma_gemm<2><<<dim3(FFn / 128, Mn / 128), 256, GEMM_SMEM>>>(
        h2h, h2l, w1h, w1l, Mn, FFn, En, b1, nullptr, nullptr, midh, midl);
    // FFN2: x2 + mid @ W2 + b2 -> out fp32
    mma_gemm<1><<<dim3(En / 128, Mn / 128), 256, GEMM_SMEM>>>(
        midh, midl, w2h, w2l, Mn, En, FFn, b2, x2, out, nullptr, nullptr);
}

// round 5
// speedup vs baseline: 3.9552x; 1.0416x over previous
#include <cuda_runtime.h>
#include <cuda_bf16.h>
#include <cstdint>
#include <cstddef>

#define Bn 2
#define Tn 2048
#define En 1024
#define Hn 16
#define HDn 64
#define FFn 4096
#define Mn (Bn*Tn)          // 4096
#define QKVN (3*En)         // 3072

// ---------------- scratch (device globals) ----------------
__device__ float g_x2[(size_t)Mn*En];                          // 16 MB fp32
__device__ __nv_bfloat16 g_qkvh[(size_t)Mn*QKVN], g_qkvl[(size_t)Mn*QKVN];
__device__ __nv_bfloat16 g_h1h[(size_t)Mn*En],  g_h1l[(size_t)Mn*En];
__device__ __nv_bfloat16 g_h2h[(size_t)Mn*En],  g_h2l[(size_t)Mn*En];
__device__ __nv_bfloat16 g_aoh[(size_t)Mn*En],  g_aol[(size_t)Mn*En];
__device__ __nv_bfloat16 g_midh[(size_t)Mn*FFn], g_midl[(size_t)Mn*FFn];
__device__ __nv_bfloat16 g_wqkvh[(size_t)QKVN*En], g_wqkvl[(size_t)QKVN*En];
__device__ __nv_bfloat16 g_wph[(size_t)En*En],   g_wpl[(size_t)En*En];
__device__ __nv_bfloat16 g_w1h[(size_t)FFn*En],  g_w1l[(size_t)FFn*En];
__device__ __nv_bfloat16 g_w2h[(size_t)En*FFn],  g_w2l[(size_t)En*FFn];

// ---------------- helpers ----------------
__device__ __forceinline__ void split_bf16(float v, __nv_bfloat16& h, __nv_bfloat16& l) {
    h = __float2bfloat16(v);
    l = __float2bfloat16(v - __bfloat162float(h));
}

__device__ __forceinline__ void split_pack(float a, float b, uint32_t& hi, uint32_t& lo) {
    __nv_bfloat16 ha = __float2bfloat16(a), hb = __float2bfloat16(b);
    __nv_bfloat16 la = __float2bfloat16(a - __bfloat162float(ha));
    __nv_bfloat16 lb = __float2bfloat16(b - __bfloat162float(hb));
    __nv_bfloat162 H = __halves2bfloat162(ha, hb), L = __halves2bfloat162(la, lb);
    hi = *reinterpret_cast<uint32_t*>(&H);
    lo = *reinterpret_cast<uint32_t*>(&L);
}

__device__ __forceinline__ uint32_t s2u(const void* p) {
    uint32_t a;
    asm("{ .reg .u64 t; cvta.to.shared.u64 t, %1; cvt.u32.u64 %0, t; }" : "=r"(a) : "l"(p));
    return a;
}

__device__ __forceinline__ void cp16(uint32_t s, const void* g) {
    asm volatile("cp.async.cg.shared.global [%0], [%1], 16;" :: "r"(s), "l"(g));
}
#define CP_COMMIT() asm volatile("cp.async.commit_group;")
#define CP_WAIT(N)  asm volatile("cp.async.wait_group %0;" :: "n"(N))

#define LDM4(r, addr) \
    asm volatile("ldmatrix.sync.aligned.m8n8.x4.shared.b16 {%0,%1,%2,%3}, [%4];" \
        : "=r"((r)[0]), "=r"((r)[1]), "=r"((r)[2]), "=r"((r)[3]) : "r"(addr))

#define LDM4T(r, addr) \
    asm volatile("ldmatrix.sync.aligned.m8n8.x4.trans.shared.b16 {%0,%1,%2,%3}, [%4];" \
        : "=r"((r)[0]), "=r"((r)[1]), "=r"((r)[2]), "=r"((r)[3]) : "r"(addr))

#define MMA_BF16(d, a, b0, b1) \
    asm volatile("mma.sync.aligned.m16n8k16.row.col.f32.bf16.bf16.f32 " \
        "{%0,%1,%2,%3}, {%4,%5,%6,%7}, {%8,%9}, {%0,%1,%2,%3};" \
        : "+f"((d)[0]), "+f"((d)[1]), "+f"((d)[2]), "+f"((d)[3]) \
        : "r"((a)[0]), "r"((a)[1]), "r"((a)[2]), "r"((a)[3]), "r"(b0), "r"(b1))

// fast exp2 for t <= 0 (degree-6 Taylor of 2^f, rel err ~1.5e-5), FMA pipe only
__device__ __forceinline__ float exp2f_fast(float t) {
    t = fmaxf(t, -126.0f);
    float fi = floorf(t);
    float f = t - fi;
    float p = 1.5403530e-4f;
    p = fmaf(p, f, 1.3333558e-3f);
    p = fmaf(p, f, 9.6181291e-3f);
    p = fmaf(p, f, 5.5504109e-2f);
    p = fmaf(p, f, 2.4022651e-1f);
    p = fmaf(p, f, 6.9314718e-1f);
    p = fmaf(p, f, 1.0f);
    return __int_as_float(__float_as_int(p) + ((int)fi << 23));
}

// ---------------- weight pack kernels (smem-tiled, coalesced both ways) ----------------
// QKV: (H,E,HD)x3 -> [N=3072 rows, K=1024 cols] hi/lo bf16
__global__ void pack_qkv_kernel(const float* __restrict__ Wq, const float* __restrict__ Wk,
                                const float* __restrict__ Wv,
                                __nv_bfloat16* __restrict__ oh, __nv_bfloat16* __restrict__ ol) {
    __shared__ float tile[32][33];
    int k0 = blockIdx.x * 32;
    int n0 = blockIdx.y * 32;
    int sel = n0 >> 10;
    int hc = n0 & 1023;
    int h = hc >> 6, e0 = hc & 63;     // e0 in {0, 32}
    const float* W = (sel == 0) ? Wq : (sel == 1) ? Wk : Wv;
    int tx = threadIdx.x, ty = threadIdx.y;
#pragma unroll
    for (int i = 0; i < 4; i++)
        tile[ty + 8 * i][tx] = W[((size_t)h * En + k0 + ty + 8 * i) * HDn + e0 + tx];
    __syncthreads();
#pragma unroll
    for (int i = 0; i < 4; i++) {
        float v = tile[tx][ty + 8 * i];
        int n = n0 + ty + 8 * i, k = k0 + tx;
        __nv_bfloat16 hi, lo; split_bf16(v, hi, lo);
        oh[(size_t)n * En + k] = hi;
        ol[(size_t)n * En + k] = lo;
    }
}

// transpose + split: In [K, N] -> out [N, K]
__global__ void pack_t_kernel(const float* __restrict__ In,
                              __nv_bfloat16* __restrict__ oh, __nv_bfloat16* __restrict__ ol,
                              int K, int N) {
    __shared__ float tile[32][33];
    int k0 = blockIdx.x * 32;
    int n0 = blockIdx.y * 32;
    int tx = threadIdx.x, ty = threadIdx.y;
#pragma unroll
    for (int i = 0; i < 4; i++)
        tile[ty + 8 * i][tx] = In[(size_t)(k0 + ty + 8 * i) * N + n0 + tx];
    __syncthreads();
#pragma unroll
    for (int i = 0; i < 4; i++) {
        float v = tile[tx][ty + 8 * i];
        int n = n0 + ty + 8 * i, k = k0 + tx;
        __nv_bfloat16 hi, lo; split_bf16(v, hi, lo);
        oh[(size_t)n * K + k] = hi;
        ol[(size_t)n * K + k] = lo;
    }
}

// ---------------- LayerNorm: fp32 in -> bf16 hi/lo out ----------------
__global__ void ln_kernel(const float* __restrict__ x, const float* __restrict__ g,
                          const float* __restrict__ b,
                          __nv_bfloat16* __restrict__ oh, __nv_bfloat16* __restrict__ ol) {
    int row = blockIdx.x;
    const float* xr = x + (size_t)row * En;
    float v[4];
    float s = 0.f, sq = 0.f;
#pragma unroll
    for (int i = 0; i < 4; i++) {
        v[i] = xr[threadIdx.x + i * 256];
        s += v[i]; sq += v[i] * v[i];
    }
    __shared__ float red[18];
#pragma unroll
    for (int o = 16; o; o >>= 1) {
        s  += __shfl_xor_sync(0xFFFFFFFFu, s,  o);
        sq += __shfl_xor_sync(0xFFFFFFFFu, sq, o);
    }
    int w = threadIdx.x >> 5, l = threadIdx.x & 31;
    if (l == 0) { red[w] = s; red[8 + w] = sq; }
    __syncthreads();
    if (threadIdx.x == 0) {
        float ts = 0.f, tq = 0.f;
#pragma unroll
        for (int i = 0; i < 8; i++) { ts += red[i]; tq += red[8 + i]; }
        red[16] = ts; red[17] = tq;
    }
    __syncthreads();
    float mean = red[16] * (1.f / En);
    float var  = red[17] * (1.f / En) - mean * mean;
    float rstd = rsqrtf(var + 1e-5f);
#pragma unroll
    for (int i = 0; i < 4; i++) {
        int c = threadIdx.x + i * 256;
        float y = (v[i] - mean) * rstd * g[c] + b[c];
        __nv_bfloat16 hi, lo; split_bf16(y, hi, lo);
        oh[(size_t)row * En + c] = hi;
        ol[(size_t)row * En + c] = lo;
    }
}

// ---------------- mma.sync GEMM: C[M,N] = (Ah+Al)[M,K] @ (Bh+Bl)^T ([N,K]) ----------------
// 128x128 CTA tile, BK=32, 4-stage cp.async ring, ONE sync per stage.
// EPI: 1 = fp32 out + bias + residual; 2 = relu(+bias) -> bf16 hi/lo; 3 = bf16 hi/lo (no bias)
template<int EPI>
__global__ void __launch_bounds__(256, 1)
mma_gemm(const __nv_bfloat16* __restrict__ Ah, const __nv_bfloat16* __restrict__ Al,
         const __nv_bfloat16* __restrict__ Bh, const __nv_bfloat16* __restrict__ Bl,
         int M, int N, int K,
         const float* __restrict__ bias, const float* __restrict__ res,
         float* __restrict__ Cf,
         __nv_bfloat16* __restrict__ Ch, __nv_bfloat16* __restrict__ Cl) {
    extern __shared__ __align__(1024) char smem[];
    const uint32_t su = s2u(smem);
    const int tid = threadIdx.x;
    const int lane = tid & 31, wid = tid >> 5;
    const int warp_m = wid & 1, warp_n = wid >> 1;
    const int brow = blockIdx.y * 128, bcol = blockIdx.x * 128;
    const int S = K >> 5;      // stages of BK=32

    const int mat = lane >> 3, rowm = lane & 7;
    const int c16bA = mat >> 1;
    const int c16bB = mat & 1;
    uint32_t mrow64[4], swmA[4];
#pragma unroll
    for (int mi = 0; mi < 4; mi++) {
        int m = warp_m * 64 + mi * 16 + (mat & 1) * 8 + rowm;
        mrow64[mi] = (uint32_t)(m * 64);
        swmA[mi] = (uint32_t)(((m >> 1) & 7) << 4);
    }
    uint32_t nrow64[2], swmB[2];
#pragma unroll
    for (int nj = 0; nj < 2; nj++) {
        int n = warp_n * 32 + nj * 16 + (mat >> 1) * 8 + rowm;
        nrow64[nj] = (uint32_t)(n * 64);
        swmB[nj] = (uint32_t)(((n >> 1) & 7) << 4);
    }

    float acc[4][4][4];
#pragma unroll
    for (int mi = 0; mi < 4; mi++)
#pragma unroll
        for (int j = 0; j < 4; j++)
#pragma unroll
            for (int r = 0; r < 4; r++) acc[mi][j][r] = 0.f;

    auto load_stage = [&](int s) {
        const int k0 = s * 32;
        const uint32_t sb = su + (uint32_t)(s & 3) * 32768;
#pragma unroll
        for (int i = 0; i < 2; i++) {
            int idx = tid + i * 256;          // 0..511
            int r = idx >> 2, c = idx & 3;
            uint32_t o = (uint32_t)(r * 64 + c * 16);
            uint32_t sw = o ^ (((o >> 7) & 7) << 4);
            size_t ao = (size_t)(brow + r) * K + k0 + c * 8;
            size_t bo = (size_t)(bcol + r) * K + k0 + c * 8;
            cp16(sb + sw,         Ah + ao);
            cp16(sb + 8192 + sw,  Al + ao);
            cp16(sb + 16384 + sw, Bh + bo);
            cp16(sb + 24576 + sw, Bl + bo);
        }
    };

    // prologue: 3 stages in flight
#pragma unroll
    for (int s = 0; s < 3; s++) { load_stage(s); CP_COMMIT(); }

    for (int s = 0; s < S; s++) {
        CP_WAIT(2);                 // stage s complete (3 groups always in flight)
        __syncthreads();            // all warps done with buffer (s-1)&3
        if (s + 3 < S) load_stage(s + 3);
        CP_COMMIT();                // always commit -> constant group count

        const uint32_t sb = su + (uint32_t)(s & 3) * 32768;
#pragma unroll
        for (int kk = 0; kk < 2; kk++) {
            uint32_t ah[4][4], al[4][4];
            const int cA = kk * 2 + c16bA;
#pragma unroll
            for (int mi = 0; mi < 4; mi++) {
                uint32_t oa = (mrow64[mi] + (uint32_t)(cA * 16)) ^ swmA[mi];
                LDM4(ah[mi], sb + oa);
                LDM4(al[mi], sb + 8192 + oa);
            }
            uint32_t bh[2][4], bl[2][4];
            const int cB = kk * 2 + c16bB;
#pragma unroll
            for (int nj = 0; nj < 2; nj++) {
                uint32_t ob = (nrow64[nj] + (uint32_t)(cB * 16)) ^ swmB[nj];
                LDM4(bh[nj], sb + 16384 + ob);
                LDM4(bl[nj], sb + 24576 + ob);
            }
#pragma unroll
            for (int mi = 0; mi < 4; mi++) {
#pragma unroll
                for (int j = 0; j < 4; j++) {
                    const int nj = j >> 1, rb = (j & 1) * 2;
                    MMA_BF16(acc[mi][j], ah[mi], bh[nj][rb], bh[nj][rb + 1]);
                    MMA_BF16(acc[mi][j], ah[mi], bl[nj][rb], bl[nj][rb + 1]);
                    MMA_BF16(acc[mi][j], al[mi], bh[nj][rb], bh[nj][rb + 1]);
                }
            }
        }
    }

    // ---------------- epilogue ----------------
    const int rowbase = brow + warp_m * 64 + (lane >> 2);
    const int colbase = bcol + warp_n * 32 + (lane & 3) * 2;
#pragma unroll
    for (int mi = 0; mi < 4; mi++) {
#pragma unroll
        for (int j = 0; j < 4; j++) {
            int col = colbase + j * 8;
            int r0 = rowbase + mi * 16;
            int r1 = r0 + 8;
            float v00 = acc[mi][j][0], v01 = acc[mi][j][1];
            float v10 = acc[mi][j][2], v11 = acc[mi][j][3];
            if (EPI == 1) {
                float b0 = bias[col], b1 = bias[col + 1];
                const float2 rr0 = *(const float2*)(res + (size_t)r0 * N + col);
                const float2 rr1 = *(const float2*)(res + (size_t)r1 * N + col);
                *(float2*)(Cf + (size_t)r0 * N + col) = make_float2(v00 + b0 + rr0.x, v01 + b1 + rr0.y);
                *(float2*)(Cf + (size_t)r1 * N + col) = make_float2(v10 + b0 + rr1.x, v11 + b1 + rr1.y);
            } else if (EPI == 2) {
                float b0 = bias[col], b1 = bias[col + 1];
                float w00 = fmaxf(v00 + b0, 0.f), w01 = fmaxf(v01 + b1, 0.f);
                float w10 = fmaxf(v10 + b0, 0.f), w11 = fmaxf(v11 + b1, 0.f);
                uint32_t h0, l0, h1, l1;
                split_pack(w00, w01, h0, l0);
                split_pack(w10, w11, h1, l1);
                *(uint32_t*)(Ch + (size_t)r0 * N + col) = h0;
                *(uint32_t*)(Cl + (size_t)r0 * N + col) = l0;
                *(uint32_t*)(Ch + (size_t)r1 * N + col) = h1;
                *(uint32_t*)(Cl + (size_t)r1 * N + col) = l1;
            } else {  // EPI == 3: raw bf16 hi/lo
                uint32_t h0, l0, h1, l1;
                split_pack(v00, v01, h0, l0);
                split_pack(v10, v11, h1, l1);
                *(uint32_t*)(Ch + (size_t)r0 * N + col) = h0;
                *(uint32_t*)(Cl + (size_t)r0 * N + col) = l0;
                *(uint32_t*)(Ch + (size_t)r1 * N + col) = h1;
                *(uint32_t*)(Cl + (size_t)r1 * N + col) = l1;
            }
        }
    }
}

// ---------------- mma.sync flash attention (causal, scale = 1/32) ----------------
// Q tile 128 x HD64 per CTA; 8 warps x 16 query rows; key chunks of 64,
// 3-stage cp.async KV ring, ONE sync per chunk. exp via FMA poly.
__global__ void __launch_bounds__(256, 1)
attn_mma(const __nv_bfloat16* __restrict__ qkvh, const __nv_bfloat16* __restrict__ qkvl,
         __nv_bfloat16* __restrict__ outh, __nv_bfloat16* __restrict__ outl) {
    extern __shared__ __align__(1024) char smem[];
    const uint32_t su = s2u(smem);
    const int tid = threadIdx.x, lane = tid & 31, w = tid >> 5;
    const int mat = lane >> 3, rowm = lane & 7;
    const uint32_t swx = (uint32_t)rowm << 4;

    const int tile = (Tn / 128 - 1) - blockIdx.x;   // biggest tiles first
    const int bh = blockIdx.y, b = bh >> 4, h = bh & 15;
    const int q0 = tile * 128;
    const int nch = 2 * (tile + 1);
    const size_t RS = QKVN;

    const __nv_bfloat16* Qh  = qkvh + ((size_t)b * Tn + q0) * RS + h * HDn;
    const __nv_bfloat16* Ql_ = qkvl + ((size_t)b * Tn + q0) * RS + h * HDn;
    const __nv_bfloat16* Kh  = qkvh + (size_t)b * Tn * RS + En + h * HDn;
    const __nv_bfloat16* Kl  = qkvl + (size_t)b * Tn * RS + En + h * HDn;
    const __nv_bfloat16* Vh  = qkvh + (size_t)b * Tn * RS + 2 * En + h * HDn;
    const __nv_bfloat16* Vl  = qkvl + (size_t)b * Tn * RS + 2 * En + h * HDn;

    // Q tile (128 x 64 bf16 hi+lo) -> smem [0, 32KB)
#pragma unroll
    for (int i = 0; i < 8; i++) {
        int idx = tid + i * 256;      // 0..2047
        int tns = idx >> 10;
        int r = (idx >> 3) & 127;
        int c = idx & 7;
        uint32_t o = (uint32_t)(r * 128 + c * 16);
        uint32_t sw = o ^ (uint32_t)((r & 7) << 4);
        const __nv_bfloat16* src = (tns ? Ql_ : Qh) + (size_t)r * RS + c * 8;
        cp16(su + (uint32_t)tns * 16384 + sw, src);
    }
    CP_COMMIT();

    auto loadKV = [&](int j) {
        const int j0 = j * 64;
        const uint32_t sb = su + 32768 + (uint32_t)(j % 3) * 32768;
#pragma unroll
        for (int i = 0; i < 8; i++) {
            int idx = tid + i * 256;   // 0..2047
            int tns = idx >> 9;        // 0..3: Kh,Kl,Vh,Vl
            int r = (idx >> 3) & 63;
            int c = idx & 7;
            uint32_t o = (uint32_t)(r * 128 + c * 16);
            uint32_t sw = o ^ (uint32_t)((r & 7) << 4);
            size_t go = (size_t)(j0 + r) * RS + c * 8;
            const __nv_bfloat16* src = (tns == 0) ? Kh + go : (tns == 1) ? Kl + go
                                     : (tns == 2) ? Vh + go : Vl + go;
            cp16(sb + (uint32_t)tns * 8192 + sw, src);
        }
    };
    loadKV(0);
    CP_COMMIT();
    loadKV(1);                // nch >= 2 always
    CP_COMMIT();
    CP_WAIT(2);               // Q complete
    __syncthreads();

    // Q fragments (persist): 4 k-steps x 4 regs, hi+lo
    uint32_t qfh[4][4], qfl[4][4];
    {
        int m = w * 16 + (mat & 1) * 8 + rowm;
#pragma unroll
        for (int s = 0; s < 4; s++) {
            uint32_t o = ((uint32_t)(m * 128 + s * 32 + (mat >> 1) * 16)) ^ swx;
            LDM4(qfh[s], su + o);
            LDM4(qfl[s], su + 16384 + o);
        }
    }

    float O[8][4];
#pragma unroll
    for (int a = 0; a < 8; a++)
#pragma unroll
        for (int r = 0; r < 4; r++) O[a][r] = 0.f;
    float m0 = -1e30f, m1 = -1e30f, l0 = 0.f, l1 = 0.f;

    const int rmin = q0 + w * 16;
    const int r0g = rmin + (lane >> 2), r1g = r0g + 8;
    const float SCL = 0.04508422f;   // log2(e) / 32

    for (int j = 0; j < nch; j++) {
        CP_WAIT(1);                  // KV chunk j complete (2 KV groups in flight)
        __syncthreads();             // all warps done with ring slot (j-1)%3
        if (j + 2 < nch) loadKV(j + 2);
        CP_COMMIT();                 // always commit

        const int j0 = j * 64;
        if (j0 <= rmin + 15) {
            const uint32_t sb = su + 32768 + (uint32_t)(j % 3) * 32768;

            // ---- S = Q K^T (3-term split) ----
            float S[8][4];
#pragma unroll
            for (int jt = 0; jt < 8; jt++)
#pragma unroll
                for (int r = 0; r < 4; r++) S[jt][r] = 0.f;
#pragma unroll
            for (int s = 0; s < 4; s++) {
                uint32_t kh4[4][4], kl4[4][4];
#pragma unroll
                for (int nb = 0; nb < 4; nb++) {
                    int n = nb * 16 + (mat >> 1) * 8 + rowm;
                    uint32_t o = ((uint32_t)(n * 128 + s * 32 + (mat & 1) * 16)) ^ swx;
                    LDM4(kh4[nb], sb + o);
                    LDM4(kl4[nb], sb + 8192 + o);
                }
#pragma unroll
                for (int nb = 0; nb < 4; nb++) {
#pragma unroll
                    for (int hf = 0; hf < 2; hf++) {
                        int jt = nb * 2 + hf;
                        MMA_BF16(S[jt], qfh[s], kh4[nb][hf * 2], kh4[nb][hf * 2 + 1]);
                        MMA_BF16(S[jt], qfh[s], kl4[nb][hf * 2], kl4[nb][hf * 2 + 1]);
                        MMA_BF16(S[jt], qfl[s], kh4[nb][hf * 2], kh4[nb][hf * 2 + 1]);
                    }
                }
            }

            // ---- scale (to log2 domain) + causal mask ----
#pragma unroll
            for (int jt = 0; jt < 8; jt++) {
                S[jt][0] *= SCL; S[jt][1] *= SCL; S[jt][2] *= SCL; S[jt][3] *= SCL;
            }
            if (j0 + 63 > rmin) {
#pragma unroll
                for (int jt = 0; jt < 8; jt++) {
                    int c0 = j0 + jt * 8 + 2 * (lane & 3);
                    if (c0 > r0g)     S[jt][0] = -1e30f;
                    if (c0 + 1 > r0g) S[jt][1] = -1e30f;
                    if (c0 > r1g)     S[jt][2] = -1e30f;
                    if (c0 + 1 > r1g) S[jt][3] = -1e30f;
                }
            }

            // ---- online softmax (base-2) ----
            float mx0 = -1e30f, mx1 = -1e30f;
#pragma unroll
            for (int jt = 0; jt < 8; jt++) {
                mx0 = fmaxf(mx0, fmaxf(S[jt][0], S[jt][1]));
                mx1 = fmaxf(mx1, fmaxf(S[jt][2], S[jt][3]));
            }
            mx0 = fmaxf(mx0, __shfl_xor_sync(0xFFFFFFFFu, mx0, 1));
            mx0 = fmaxf(mx0, __shfl_xor_sync(0xFFFFFFFFu, mx0, 2));
            mx1 = fmaxf(mx1, __shfl_xor_sync(0xFFFFFFFFu, mx1, 1));
            mx1 = fmaxf(mx1, __shfl_xor_sync(0xFFFFFFFFu, mx1, 2));
            float mn0 = fmaxf(m0, mx0), mn1 = fmaxf(m1, mx1);
            float al0 = exp2f_fast(m0 - mn0), al1 = exp2f_fast(m1 - mn1);
            m0 = mn0; m1 = mn1;
            float s0 = 0.f, s1 = 0.f;
#pragma unroll
            for (int jt = 0; jt < 8; jt++) {
                float p0 = exp2f_fast(S[jt][0] - mn0); S[jt][0] = p0;
                float p1 = exp2f_fast(S[jt][1] - mn0); S[jt][1] = p1;
                float p2 = exp2f_fast(S[jt][2] - mn1); S[jt][2] = p2;
                float p3 = exp2f_fast(S[jt][3] - mn1); S[jt][3] = p3;
                s0 += p0 + p1; s1 += p2 + p3;
            }
            s0 += __shfl_xor_sync(0xFFFFFFFFu, s0, 1);
            s0 += __shfl_xor_sync(0xFFFFFFFFu, s0, 2);
            s1 += __shfl_xor_sync(0xFFFFFFFFu, s1, 1);
            s1 += __shfl_xor_sync(0xFFFFFFFFu, s1, 2);
            l0 = l0 * al0 + s0;
            l1 = l1 * al1 + s1;
#pragma unroll
            for (int dt = 0; dt < 8; dt++) {
                O[dt][0] *= al0; O[dt][1] *= al0; O[dt][2] *= al1; O[dt][3] *= al1;
            }

            // ---- O += P V (3-term split) ----
#pragma unroll
            for (int s = 0; s < 4; s++) {
                const int t0 = 2 * s, t1 = 2 * s + 1;
                uint32_t ph[4], pl[4];
                split_pack(S[t0][0], S[t0][1], ph[0], pl[0]);
                split_pack(S[t0][2], S[t0][3], ph[1], pl[1]);
                split_pack(S[t1][0], S[t1][1], ph[2], pl[2]);
                split_pack(S[t1][2], S[t1][3], ph[3], pl[3]);
                uint32_t vh4[4][4], vl4[4][4];
#pragma unroll
                for (int nb = 0; nb < 4; nb++) {
                    int kr = s * 16 + (mat & 1) * 8 + rowm;
                    uint32_t o = ((uint32_t)(kr * 128 + (nb * 16 + (mat >> 1) * 8) * 2)) ^ swx;
                    LDM4T(vh4[nb], sb + 16384 + o);
                    LDM4T(vl4[nb], sb + 24576 + o);
                }
#pragma unroll
                for (int nb = 0; nb < 4; nb++) {
#pragma unroll
                    for (int hf = 0; hf < 2; hf++) {
                        int dt = nb * 2 + hf;
                        MMA_BF16(O[dt], ph, vh4[nb][hf * 2], vh4[nb][hf * 2 + 1]);
                        MMA_BF16(O[dt], ph, vl4[nb][hf * 2], vl4[nb][hf * 2 + 1]);
                        MMA_BF16(O[dt], pl, vh4[nb][hf * 2], vh4[nb][hf * 2 + 1]);
                    }
                }
            }
        }
    }

    // ---- normalize + store bf16 hi/lo ----
    float inv0 = 1.f / l0, inv1 = 1.f / l1;
#pragma unroll
    for (int dt = 0; dt < 8; dt++) {
        int col = h * 64 + dt * 8 + 2 * (lane & 3);
        size_t o0 = ((size_t)b * Tn + r0g) * En + col;
        size_t o1 = ((size_t)b * Tn + r1g) * En + col;
        uint32_t hA, lA, hB, lB;
        split_pack(O[dt][0] * inv0, O[dt][1] * inv0, hA, lA);
        split_pack(O[dt][2] * inv1, O[dt][3] * inv1, hB, lB);
        *(uint32_t*)(outh + o0) = hA; *(uint32_t*)(outl + o0) = lA;
        *(uint32_t*)(outh + o1) = hB; *(uint32_t*)(outl + o1) = lB;
    }
}

// ---------------- launch ----------------
extern "C" void kernel_launch(void* const* d_in, const int* in_sizes, int n_in,
                              void* d_out, int out_size) {
    const float* x     = (const float*)d_in[0];
    const float* Wq    = (const float*)d_in[1];
    const float* Wk    = (const float*)d_in[2];
    const float* Wv    = (const float*)d_in[3];
    const float* Wproj = (const float*)d_in[4];
    const float* bproj = (const float*)d_in[5];
    const float* W1    = (const float*)d_in[6];
    const float* b1    = (const float*)d_in[7];
    const float* W2    = (const float*)d_in[8];
    const float* b2    = (const float*)d_in[9];
    const float* g1    = (const float*)d_in[10];
    const float* be1   = (const float*)d_in[11];
    const float* g2    = (const float*)d_in[12];
    const float* be2   = (const float*)d_in[13];
    float* out = (float*)d_out;

    float *x2;
    __nv_bfloat16 *qkvh, *qkvl, *h1h, *h1l, *h2h, *h2l, *aoh, *aol, *midh, *midl;
    __nv_bfloat16 *wqkvh, *wqkvl, *wph, *wpl, *w1h, *w1l, *w2h, *w2l;
    cudaGetSymbolAddress((void**)&x2,    g_x2);
    cudaGetSymbolAddress((void**)&qkvh,  g_qkvh);  cudaGetSymbolAddress((void**)&qkvl, g_qkvl);
    cudaGetSymbolAddress((void**)&h1h,   g_h1h);   cudaGetSymbolAddress((void**)&h1l,  g_h1l);
    cudaGetSymbolAddress((void**)&h2h,   g_h2h);   cudaGetSymbolAddress((void**)&h2l,  g_h2l);
    cudaGetSymbolAddress((void**)&aoh,   g_aoh);   cudaGetSymbolAddress((void**)&aol,  g_aol);
    cudaGetSymbolAddress((void**)&midh,  g_midh);  cudaGetSymbolAddress((void**)&midl, g_midl);
    cudaGetSymbolAddress((void**)&wqkvh, g_wqkvh); cudaGetSymbolAddress((void**)&wqkvl, g_wqkvl);
    cudaGetSymbolAddress((void**)&wph,   g_wph);   cudaGetSymbolAddress((void**)&wpl,  g_wpl);
    cudaGetSymbolAddress((void**)&w1h,   g_w1h);   cudaGetSymbolAddress((void**)&w1l,  g_w1l);
    cudaGetSymbolAddress((void**)&w2h,   g_w2h);   cudaGetSymbolAddress((void**)&w2l,  g_w2l);

    const int GEMM_SMEM = 4 * 32768;   // 128KB, 4-stage ring
    cudaFuncSetAttribute(mma_gemm<1>, cudaFuncAttributeMaxDynamicSharedMemorySize, GEMM_SMEM);
    cudaFuncSetAttribute(mma_gemm<2>, cudaFuncAttributeMaxDynamicSharedMemorySize, GEMM_SMEM);
    cudaFuncSetAttribute(mma_gemm<3>, cudaFuncAttributeMaxDynamicSharedMemorySize, GEMM_SMEM);
    const int ATTN_SMEM = 32768 + 3 * 32768;   // Q 32KB + 3-stage KV ring 96KB
    cudaFuncSetAttribute(attn_mma, cudaFuncAttributeMaxDynamicSharedMemorySize, ATTN_SMEM);

    // weight packs (hi/lo bf16, [N,K] layout) — smem-tiled transposes
    pack_qkv_kernel<<<dim3(En / 32, QKVN / 32), dim3(32, 8)>>>(Wq, Wk, Wv, wqkvh, wqkvl);
    pack_t_kernel<<<dim3(En / 32, En / 32),  dim3(32, 8)>>>(Wproj, wph, wpl, En, En);
    pack_t_kernel<<<dim3(En / 32, FFn / 32), dim3(32, 8)>>>(W1, w1h, w1l, En, FFn);
    pack_t_kernel<<<dim3(FFn / 32, En / 32), dim3(32, 8)>>>(W2, w2h, w2l, FFn, En);

    // LN1 -> h1 hi/lo
    ln_kernel<<<Mn, 256>>>(x, g1, be1, h1h, h1l);
    // QKV GEMM: -> qkv bf16 hi/lo
    mma_gemm<3><<<dim3(QKVN / 128, Mn / 128), 256, GEMM_SMEM>>>(
        h1h, h1l, wqkvh, wqkvl, Mn, QKVN, En, nullptr, nullptr, nullptr, qkvh, qkvl);
    // flash attention -> attno hi/lo
    attn_mma<<<dim3(Tn / 128, Bn * Hn), 256, ATTN_SMEM>>>(qkvh, qkvl, aoh, aol);
    // proj + bias + residual(x) -> x2 fp32
    mma_gemm<1><<<dim3(En / 128, Mn / 128), 256, GEMM_SMEM>>>(
        aoh, aol, wph, wpl, Mn, En, En, bproj, x, x2, nullptr, nullptr);
    // LN2 -> h2 hi/lo
    ln_kernel<<<Mn, 256>>>(x2, g2, be2, h2h, h2l);
    // FFN1: relu(h2 @ W1 + b1) -> mid hi/lo
    mma_gemm<2><<<dim3(FFn / 128, Mn / 128), 256, GEMM_SMEM>>>(
        h2h, h2l, w1h, w1l, Mn, FFn, En, b1, nullptr, nullptr, midh, midl);
    // FFN2: x2 + mid @ W2 + b2 -> out fp32
    mma_gemm<1><<<dim3(En / 128, Mn / 128), 256, GEMM_SMEM>>>(
        midh, midl, w2h, w2l, Mn, En, FFn, b2, x2, out, nullptr, nullptr);
}

// round 6
// speedup vs baseline: 5.2401x; 1.3249x over previous
#include <cuda_runtime.h>
#include <cuda_fp16.h>
#include <cstdint>
#include <cstddef>

#define Bn 2
#define Tn 2048
#define En 1024
#define Hn 16
#define HDn 64
#define FFn 4096
#define Mn (Bn*Tn)          // 4096
#define QKVN (3*En)         // 3072

// ---------------- scratch (device globals) ----------------
__device__ float g_x2[(size_t)Mn*En];                       // 16 MB fp32
__device__ __half g_qkvh[(size_t)Mn*QKVN], g_qkvl[(size_t)Mn*QKVN];
__device__ __half g_h1h[(size_t)Mn*En],  g_h1l[(size_t)Mn*En];
__device__ __half g_h2h[(size_t)Mn*En],  g_h2l[(size_t)Mn*En];
__device__ __half g_aoh[(size_t)Mn*En],  g_aol[(size_t)Mn*En];
__device__ __half g_midh[(size_t)Mn*FFn], g_midl[(size_t)Mn*FFn];
__device__ __half g_wqkv[(size_t)QKVN*En];   // weights: single fp16, [N,K]
__device__ __half g_wp[(size_t)En*En];
__device__ __half g_w1[(size_t)FFn*En];
__device__ __half g_w2[(size_t)En*FFn];

// ---------------- helpers ----------------
__device__ __forceinline__ void split_f16(float v, __half& h, __half& l) {
    h = __float2half_rn(v);
    l = __float2half_rn(v - __half2float(h));
}

__device__ __forceinline__ void split_pack(float a, float b, uint32_t& hi, uint32_t& lo) {
    __half ha = __float2half_rn(a), hb = __float2half_rn(b);
    __half la = __float2half_rn(a - __half2float(ha));
    __half lb = __float2half_rn(b - __half2float(hb));
    __half2 H = __halves2half2(ha, hb), L = __halves2half2(la, lb);
    hi = *reinterpret_cast<uint32_t*>(&H);
    lo = *reinterpret_cast<uint32_t*>(&L);
}

__device__ __forceinline__ uint32_t s2u(const void* p) {
    uint32_t a;
    asm("{ .reg .u64 t; cvta.to.shared.u64 t, %1; cvt.u32.u64 %0, t; }" : "=r"(a) : "l"(p));
    return a;
}

__device__ __forceinline__ void cp16(uint32_t s, const void* g) {
    asm volatile("cp.async.cg.shared.global [%0], [%1], 16;" :: "r"(s), "l"(g));
}
#define CP_COMMIT() asm volatile("cp.async.commit_group;")
#define CP_WAIT(N)  asm volatile("cp.async.wait_group %0;" :: "n"(N))

#define LDM4(r, addr) \
    asm volatile("ldmatrix.sync.aligned.m8n8.x4.shared.b16 {%0,%1,%2,%3}, [%4];" \
        : "=r"((r)[0]), "=r"((r)[1]), "=r"((r)[2]), "=r"((r)[3]) : "r"(addr))

#define LDM4T(r, addr) \
    asm volatile("ldmatrix.sync.aligned.m8n8.x4.trans.shared.b16 {%0,%1,%2,%3}, [%4];" \
        : "=r"((r)[0]), "=r"((r)[1]), "=r"((r)[2]), "=r"((r)[3]) : "r"(addr))

#define MMA_F16(d, a, b0, b1) \
    asm volatile("mma.sync.aligned.m16n8k16.row.col.f32.f16.f16.f32 " \
        "{%0,%1,%2,%3}, {%4,%5,%6,%7}, {%8,%9}, {%0,%1,%2,%3};" \
        : "+f"((d)[0]), "+f"((d)[1]), "+f"((d)[2]), "+f"((d)[3]) \
        : "r"((a)[0]), "r"((a)[1]), "r"((a)[2]), "r"((a)[3]), "r"(b0), "r"(b1))

// fast exp2 for t <= 0 (degree-6 Taylor of 2^f, rel err ~1.5e-5), FMA pipe only
__device__ __forceinline__ float exp2f_fast(float t) {
    t = fmaxf(t, -126.0f);
    float fi = floorf(t);
    float f = t - fi;
    float p = 1.5403530e-4f;
    p = fmaf(p, f, 1.3333558e-3f);
    p = fmaf(p, f, 9.6181291e-3f);
    p = fmaf(p, f, 5.5504109e-2f);
    p = fmaf(p, f, 2.4022651e-1f);
    p = fmaf(p, f, 6.9314718e-1f);
    p = fmaf(p, f, 1.0f);
    return __int_as_float(__float_as_int(p) + ((int)fi << 23));
}

// ---------------- weight pack kernels (smem-tiled, single fp16 out) ----------------
// QKV: (H,E,HD)x3 -> [N=3072 rows, K=1024 cols] fp16
__global__ void pack_qkv_kernel(const float* __restrict__ Wq, const float* __restrict__ Wk,
                                const float* __restrict__ Wv, __half* __restrict__ o) {
    __shared__ float tile[32][33];
    int k0 = blockIdx.x * 32;
    int n0 = blockIdx.y * 32;
    int sel = n0 >> 10;
    int hc = n0 & 1023;
    int h = hc >> 6, e0 = hc & 63;
    const float* W = (sel == 0) ? Wq : (sel == 1) ? Wk : Wv;
    int tx = threadIdx.x, ty = threadIdx.y;
#pragma unroll
    for (int i = 0; i < 4; i++)
        tile[ty + 8 * i][tx] = W[((size_t)h * En + k0 + ty + 8 * i) * HDn + e0 + tx];
    __syncthreads();
#pragma unroll
    for (int i = 0; i < 4; i++) {
        int n = n0 + ty + 8 * i, k = k0 + tx;
        o[(size_t)n * En + k] = __float2half_rn(tile[tx][ty + 8 * i]);
    }
}

// transpose: In [K, N] -> out [N, K] fp16
__global__ void pack_t_kernel(const float* __restrict__ In, __half* __restrict__ o,
                              int K, int N) {
    __shared__ float tile[32][33];
    int k0 = blockIdx.x * 32;
    int n0 = blockIdx.y * 32;
    int tx = threadIdx.x, ty = threadIdx.y;
#pragma unroll
    for (int i = 0; i < 4; i++)
        tile[ty + 8 * i][tx] = In[(size_t)(k0 + ty + 8 * i) * N + n0 + tx];
    __syncthreads();
#pragma unroll
    for (int i = 0; i < 4; i++) {
        int n = n0 + ty + 8 * i, k = k0 + tx;
        o[(size_t)n * K + k] = __float2half_rn(tile[tx][ty + 8 * i]);
    }
}

// ---------------- LayerNorm: fp32 in -> fp16 hi/lo out ----------------
__global__ void ln_kernel(const float* __restrict__ x, const float* __restrict__ g,
                          const float* __restrict__ b,
                          __half* __restrict__ oh, __half* __restrict__ ol) {
    int row = blockIdx.x;
    const float* xr = x + (size_t)row * En;
    float v[4];
    float s = 0.f, sq = 0.f;
#pragma unroll
    for (int i = 0; i < 4; i++) {
        v[i] = xr[threadIdx.x + i * 256];
        s += v[i]; sq += v[i] * v[i];
    }
    __shared__ float red[18];
#pragma unroll
    for (int o = 16; o; o >>= 1) {
        s  += __shfl_xor_sync(0xFFFFFFFFu, s,  o);
        sq += __shfl_xor_sync(0xFFFFFFFFu, sq, o);
    }
    int w = threadIdx.x >> 5, l = threadIdx.x & 31;
    if (l == 0) { red[w] = s; red[8 + w] = sq; }
    __syncthreads();
    if (threadIdx.x == 0) {
        float ts = 0.f, tq = 0.f;
#pragma unroll
        for (int i = 0; i < 8; i++) { ts += red[i]; tq += red[8 + i]; }
        red[16] = ts; red[17] = tq;
    }
    __syncthreads();
    float mean = red[16] * (1.f / En);
    float var  = red[17] * (1.f / En) - mean * mean;
    float rstd = rsqrtf(var + 1e-5f);
#pragma unroll
    for (int i = 0; i < 4; i++) {
        int c = threadIdx.x + i * 256;
        float y = (v[i] - mean) * rstd * g[c] + b[c];
        __half hi, lo; split_f16(y, hi, lo);
        oh[(size_t)row * En + c] = hi;
        ol[(size_t)row * En + c] = lo;
    }
}

// ---------------- mma.sync GEMM: C[M,N] = (Ah+Al)[M,K] @ Bh^T ([N,K]) ----------------
// 128x128 CTA tile, BK=32, 4-stage cp.async ring (24KB/stage), ONE sync per stage.
// 2-term fp16 split: D = Ah*Bh + Al*Bh.
// EPI: 1 = fp32 out + bias + residual; 2 = relu(+bias) -> fp16 hi/lo; 3 = fp16 hi/lo
template<int EPI>
__global__ void __launch_bounds__(256, 1)
mma_gemm(const __half* __restrict__ Ah, const __half* __restrict__ Al,
         const __half* __restrict__ Bh,
         int M, int N, int K,
         const float* __restrict__ bias, const float* __restrict__ res,
         float* __restrict__ Cf,
         __half* __restrict__ Ch, __half* __restrict__ Cl) {
    extern __shared__ __align__(1024) char smem[];
    const uint32_t su = s2u(smem);
    const int tid = threadIdx.x;
    const int lane = tid & 31, wid = tid >> 5;
    const int warp_m = wid & 1, warp_n = wid >> 1;
    const int brow = blockIdx.y * 128, bcol = blockIdx.x * 128;
    const int S = K >> 5;      // stages of BK=32

    const int mat = lane >> 3, rowm = lane & 7;
    const int c16bA = mat >> 1;
    const int c16bB = mat & 1;
    uint32_t mrow64[4], swmA[4];
#pragma unroll
    for (int mi = 0; mi < 4; mi++) {
        int m = warp_m * 64 + mi * 16 + (mat & 1) * 8 + rowm;
        mrow64[mi] = (uint32_t)(m * 64);
        swmA[mi] = (uint32_t)(((m >> 1) & 7) << 4);
    }
    uint32_t nrow64[2], swmB[2];
#pragma unroll
    for (int nj = 0; nj < 2; nj++) {
        int n = warp_n * 32 + nj * 16 + (mat >> 1) * 8 + rowm;
        nrow64[nj] = (uint32_t)(n * 64);
        swmB[nj] = (uint32_t)(((n >> 1) & 7) << 4);
    }

    float acc[4][4][4];
#pragma unroll
    for (int mi = 0; mi < 4; mi++)
#pragma unroll
        for (int j = 0; j < 4; j++)
#pragma unroll
            for (int r = 0; r < 4; r++) acc[mi][j][r] = 0.f;

    // stage: Ah@0 (8K), Al@8192, Bh@16384; 24KB per stage
    auto load_stage = [&](int s) {
        const int k0 = s * 32;
        const uint32_t sb = su + (uint32_t)(s & 3) * 24576;
#pragma unroll
        for (int i = 0; i < 6; i++) {
            int idx = tid + i * 256;          // 0..1535
            int tns = idx >> 9;               // 0=Ah 1=Al 2=Bh
            int sub = idx & 511;
            int r = sub >> 2, c = sub & 3;
            uint32_t o = (uint32_t)(r * 64 + c * 16);
            uint32_t sw = o ^ (((o >> 7) & 7) << 4);
            const __half* src = (tns == 0) ? Ah + (size_t)(brow + r) * K + k0 + c * 8
                              : (tns == 1) ? Al + (size_t)(brow + r) * K + k0 + c * 8
                                           : Bh + (size_t)(bcol + r) * K + k0 + c * 8;
            cp16(sb + (uint32_t)tns * 8192 + sw, src);
        }
    };

    // prologue: 3 stages in flight
#pragma unroll
    for (int s = 0; s < 3; s++) { load_stage(s); CP_COMMIT(); }

    for (int s = 0; s < S; s++) {
        CP_WAIT(2);
        __syncthreads();
        if (s + 3 < S) load_stage(s + 3);
        CP_COMMIT();

        const uint32_t sb = su + (uint32_t)(s & 3) * 24576;
#pragma unroll
        for (int kk = 0; kk < 2; kk++) {
            uint32_t ah[4][4], al[4][4];
            const int cA = kk * 2 + c16bA;
#pragma unroll
            for (int mi = 0; mi < 4; mi++) {
                uint32_t oa = (mrow64[mi] + (uint32_t)(cA * 16)) ^ swmA[mi];
                LDM4(ah[mi], sb + oa);
                LDM4(al[mi], sb + 8192 + oa);
            }
            uint32_t bh[2][4];
            const int cB = kk * 2 + c16bB;
#pragma unroll
            for (int nj = 0; nj < 2; nj++) {
                uint32_t ob = (nrow64[nj] + (uint32_t)(cB * 16)) ^ swmB[nj];
                LDM4(bh[nj], sb + 16384 + ob);
            }
#pragma unroll
            for (int mi = 0; mi < 4; mi++) {
#pragma unroll
                for (int j = 0; j < 4; j++) {
                    const int nj = j >> 1, rb = (j & 1) * 2;
                    MMA_F16(acc[mi][j], ah[mi], bh[nj][rb], bh[nj][rb + 1]);
                    MMA_F16(acc[mi][j], al[mi], bh[nj][rb], bh[nj][rb + 1]);
                }
            }
        }
    }

    // ---------------- epilogue ----------------
    const int rowbase = brow + warp_m * 64 + (lane >> 2);
    const int colbase = bcol + warp_n * 32 + (lane & 3) * 2;
#pragma unroll
    for (int mi = 0; mi < 4; mi++) {
#pragma unroll
        for (int j = 0; j < 4; j++) {
            int col = colbase + j * 8;
            int r0 = rowbase + mi * 16;
            int r1 = r0 + 8;
            float v00 = acc[mi][j][0], v01 = acc[mi][j][1];
            float v10 = acc[mi][j][2], v11 = acc[mi][j][3];
            if (EPI == 1) {
                float b0 = bias[col], b1 = bias[col + 1];
                const float2 rr0 = *(const float2*)(res + (size_t)r0 * N + col);
                const float2 rr1 = *(const float2*)(res + (size_t)r1 * N + col);
                *(float2*)(Cf + (size_t)r0 * N + col) = make_float2(v00 + b0 + rr0.x, v01 + b1 + rr0.y);
                *(float2*)(Cf + (size_t)r1 * N + col) = make_float2(v10 + b0 + rr1.x, v11 + b1 + rr1.y);
            } else if (EPI == 2) {
                float b0 = bias[col], b1 = bias[col + 1];
                float w00 = fmaxf(v00 + b0, 0.f), w01 = fmaxf(v01 + b1, 0.f);
                float w10 = fmaxf(v10 + b0, 0.f), w11 = fmaxf(v11 + b1, 0.f);
                uint32_t h0, l0, h1, l1;
                split_pack(w00, w01, h0, l0);
                split_pack(w10, w11, h1, l1);
                *(uint32_t*)(Ch + (size_t)r0 * N + col) = h0;
                *(uint32_t*)(Cl + (size_t)r0 * N + col) = l0;
                *(uint32_t*)(Ch + (size_t)r1 * N + col) = h1;
                *(uint32_t*)(Cl + (size_t)r1 * N + col) = l1;
            } else {  // EPI == 3: raw fp16 hi/lo
                uint32_t h0, l0, h1, l1;
                split_pack(v00, v01, h0, l0);
                split_pack(v10, v11, h1, l1);
                *(uint32_t*)(Ch + (size_t)r0 * N + col) = h0;
                *(uint32_t*)(Cl + (size_t)r0 * N + col) = l0;
                *(uint32_t*)(Ch + (size_t)r1 * N + col) = h1;
                *(uint32_t*)(Cl + (size_t)r1 * N + col) = l1;
            }
        }
    }
}

// ---------------- mma.sync flash attention (causal, scale = 1/32) ----------------
// Q tile 128 x HD64 per CTA; 8 warps x 16 query rows; key chunks of 64,
// 3-stage cp.async KV ring (Kh+Vh = 16KB/chunk), ONE sync per chunk.
// 2-term fp16: S = (Qh+Ql)Kh, O = (Ph+Pl)Vh.
__global__ void __launch_bounds__(256, 1)
attn_mma(const __half* __restrict__ qkvh, const __half* __restrict__ qkvl,
         __half* __restrict__ outh, __half* __restrict__ outl) {
    extern __shared__ __align__(1024) char smem[];
    const uint32_t su = s2u(smem);
    const int tid = threadIdx.x, lane = tid & 31, w = tid >> 5;
    const int mat = lane >> 3, rowm = lane & 7;
    const uint32_t swx = (uint32_t)rowm << 4;

    const int tile = (Tn / 128 - 1) - blockIdx.x;   // biggest tiles first
    const int bh = blockIdx.y, b = bh >> 4, h = bh & 15;
    const int q0 = tile * 128;
    const int nch = 2 * (tile + 1);
    const size_t RS = QKVN;

    const __half* Qh  = qkvh + ((size_t)b * Tn + q0) * RS + h * HDn;
    const __half* Ql_ = qkvl + ((size_t)b * Tn + q0) * RS + h * HDn;
    const __half* Kh  = qkvh + (size_t)b * Tn * RS + En + h * HDn;
    const __half* Vh  = qkvh + (size_t)b * Tn * RS + 2 * En + h * HDn;

    // Q tile (128 x 64 fp16 hi+lo) -> smem [0, 32KB)
#pragma unroll
    for (int i = 0; i < 8; i++) {
        int idx = tid + i * 256;      // 0..2047
        int tns = idx >> 10;
        int r = (idx >> 3) & 127;
        int c = idx & 7;
        uint32_t o = (uint32_t)(r * 128 + c * 16);
        uint32_t sw = o ^ (uint32_t)((r & 7) << 4);
        const __half* src = (tns ? Ql_ : Qh) + (size_t)r * RS + c * 8;
        cp16(su + (uint32_t)tns * 16384 + sw, src);
    }
    CP_COMMIT();

    // KV ring: 3 slots of 16KB (Kh 8KB + Vh 8KB) at su+32768
    auto loadKV = [&](int j) {
        const int j0 = j * 64;
        const uint32_t sb = su + 32768 + (uint32_t)(j % 3) * 16384;
#pragma unroll
        for (int i = 0; i < 4; i++) {
            int idx = tid + i * 256;   // 0..1023
            int tns = idx >> 9;        // 0=Kh 1=Vh
            int sub = idx & 511;
            int r = sub >> 3, c = sub & 7;
            uint32_t o = (uint32_t)(r * 128 + c * 16);
            uint32_t sw = o ^ (uint32_t)((r & 7) << 4);
            size_t go = (size_t)(j0 + r) * RS + c * 8;
            const __half* src = (tns == 0) ? Kh + go : Vh + go;
            cp16(sb + (uint32_t)tns * 8192 + sw, src);
        }
    };
    loadKV(0);
    CP_COMMIT();
    loadKV(1);                // nch >= 2 always
    CP_COMMIT();
    CP_WAIT(2);               // Q complete
    __syncthreads();

    // Q fragments (persist): 4 k-steps x 4 regs, hi+lo
    uint32_t qfh[4][4], qfl[4][4];
    {
        int m = w * 16 + (mat & 1) * 8 + rowm;
#pragma unroll
        for (int s = 0; s < 4; s++) {
            uint32_t o = ((uint32_t)(m * 128 + s * 32 + (mat >> 1) * 16)) ^ swx;
            LDM4(qfh[s], su + o);
            LDM4(qfl[s], su + 16384 + o);
        }
    }

    float O[8][4];
#pragma unroll
    for (int a = 0; a < 8; a++)
#pragma unroll
        for (int r = 0; r < 4; r++) O[a][r] = 0.f;
    float m0 = -1e30f, m1 = -1e30f, l0 = 0.f, l1 = 0.f;

    const int rmin = q0 + w * 16;
    const int r0g = rmin + (lane >> 2), r1g = r0g + 8;
    const float SCL = 0.04508422f;   // log2(e) / 32

    for (int j = 0; j < nch; j++) {
        CP_WAIT(1);
        __syncthreads();
        if (j + 2 < nch) loadKV(j + 2);
        CP_COMMIT();

        const int j0 = j * 64;
        if (j0 <= rmin + 15) {
            const uint32_t sb = su + 32768 + (uint32_t)(j % 3) * 16384;

            // ---- S = Q K^T (2-term) ----
            float S[8][4];
#pragma unroll
            for (int jt = 0; jt < 8; jt++)
#pragma unroll
                for (int r = 0; r < 4; r++) S[jt][r] = 0.f;
#pragma unroll
            for (int s = 0; s < 4; s++) {
                uint32_t kh4[4][4];
#pragma unroll
                for (int nb = 0; nb < 4; nb++) {
                    int n = nb * 16 + (mat >> 1) * 8 + rowm;
                    uint32_t o = ((uint32_t)(n * 128 + s * 32 + (mat & 1) * 16)) ^ swx;
                    LDM4(kh4[nb], sb + o);
                }
#pragma unroll
                for (int nb = 0; nb < 4; nb++) {
#pragma unroll
                    for (int hf = 0; hf < 2; hf++) {
                        int jt = nb * 2 + hf;
                        MMA_F16(S[jt], qfh[s], kh4[nb][hf * 2], kh4[nb][hf * 2 + 1]);
                        MMA_F16(S[jt], qfl[s], kh4[nb][hf * 2], kh4[nb][hf * 2 + 1]);
                    }
                }
            }

            // ---- scale (to log2 domain) + causal mask ----
#pragma unroll
            for (int jt = 0; jt < 8; jt++) {
                S[jt][0] *= SCL; S[jt][1] *= SCL; S[jt][2] *= SCL; S[jt][3] *= SCL;
            }
            if (j0 + 63 > rmin) {
#pragma unroll
                for (int jt = 0; jt < 8; jt++) {
                    int c0 = j0 + jt * 8 + 2 * (lane & 3);
                    if (c0 > r0g)     S[jt][0] = -1e30f;
                    if (c0 + 1 > r0g) S[jt][1] = -1e30f;
                    if (c0 > r1g)     S[jt][2] = -1e30f;
                    if (c0 + 1 > r1g) S[jt][3] = -1e30f;
                }
            }

            // ---- online softmax (base-2) ----
            float mx0 = -1e30f, mx1 = -1e30f;
#pragma unroll
            for (int jt = 0; jt < 8; jt++) {
                mx0 = fmaxf(mx0, fmaxf(S[jt][0], S[jt][1]));
                mx1 = fmaxf(mx1, fmaxf(S[jt][2], S[jt][3]));
            }
            mx0 = fmaxf(mx0, __shfl_xor_sync(0xFFFFFFFFu, mx0, 1));
            mx0 = fmaxf(mx0, __shfl_xor_sync(0xFFFFFFFFu, mx0, 2));
            mx1 = fmaxf(mx1, __shfl_xor_sync(0xFFFFFFFFu, mx1, 1));
            mx1 = fmaxf(mx1, __shfl_xor_sync(0xFFFFFFFFu, mx1, 2));
            float mn0 = fmaxf(m0, mx0), mn1 = fmaxf(m1, mx1);
            float al0 = exp2f_fast(m0 - mn0), al1 = exp2f_fast(m1 - mn1);
            m0 = mn0; m1 = mn1;
            float s0 = 0.f, s1 = 0.f;
#pragma unroll
            for (int jt = 0; jt < 8; jt++) {
                float p0 = exp2f_fast(S[jt][0] - mn0); S[jt][0] = p0;
                float p1 = exp2f_fast(S[jt][1] - mn0); S[jt][1] = p1;
                float p2 = exp2f_fast(S[jt][2] - mn1); S[jt][2] = p2;
                float p3 = exp2f_fast(S[jt][3] - mn1); S[jt][3] = p3;
                s0 += p0 + p1; s1 += p2 + p3;
            }
            s0 += __shfl_xor_sync(0xFFFFFFFFu, s0, 1);
            s0 += __shfl_xor_sync(0xFFFFFFFFu, s0, 2);
            s1 += __shfl_xor_sync(0xFFFFFFFFu, s1, 1);
            s1 += __shfl_xor_sync(0xFFFFFFFFu, s1, 2);
            l0 = l0 * al0 + s0;
            l1 = l1 * al1 + s1;
#pragma unroll
            for (int dt = 0; dt < 8; dt++) {
                O[dt][0] *= al0; O[dt][1] *= al0; O[dt][2] *= al1; O[dt][3] *= al1;
            }

            // ---- O += P V (2-term) ----
#pragma unroll
            for (int s = 0; s < 4; s++) {
                const int t0 = 2 * s, t1 = 2 * s + 1;
                uint32_t ph[4], pl[4];
                split_pack(S[t0][0], S[t0][1], ph[0], pl[0]);
                split_pack(S[t0][2], S[t0][3], ph[1], pl[1]);
                split_pack(S[t1][0], S[t1][1], ph[2], pl[2]);
                split_pack(S[t1][2], S[t1][3], ph[3], pl[3]);
                uint32_t vh4[4][4];
#pragma unroll
                for (int nb = 0; nb < 4; nb++) {
                    int kr = s * 16 + (mat & 1) * 8 + rowm;
                    uint32_t o = ((uint32_t)(kr * 128 + (nb * 16 + (mat >> 1) * 8) * 2)) ^ swx;
                    LDM4T(vh4[nb], sb + 8192 + o);
                }
#pragma unroll
                for (int nb = 0; nb < 4; nb++) {
#pragma unroll
                    for (int hf = 0; hf < 2; hf++) {
                        int dt = nb * 2 + hf;
                        MMA_F16(O[dt], ph, vh4[nb][hf * 2], vh4[nb][hf * 2 + 1]);
                        MMA_F16(O[dt], pl, vh4[nb][hf * 2], vh4[nb][hf * 2 + 1]);
                    }
                }
            }
        }
    }

    // ---- normalize + store fp16 hi/lo ----
    float inv0 = 1.f / l0, inv1 = 1.f / l1;
#pragma unroll
    for (int dt = 0; dt < 8; dt++) {
        int col = h * 64 + dt * 8 + 2 * (lane & 3);
        size_t o0 = ((size_t)b * Tn + r0g) * En + col;
        size_t o1 = ((size_t)b * Tn + r1g) * En + col;
        uint32_t hA, lA, hB, lB;
        split_pack(O[dt][0] * inv0, O[dt][1] * inv0, hA, lA);
        split_pack(O[dt][2] * inv1, O[dt][3] * inv1, hB, lB);
        *(uint32_t*)(outh + o0) = hA; *(uint32_t*)(outl + o0) = lA;
        *(uint32_t*)(outh + o1) = hB; *(uint32_t*)(outl + o1) = lB;
    }
}

// ---------------- launch ----------------
extern "C" void kernel_launch(void* const* d_in, const int* in_sizes, int n_in,
                              void* d_out, int out_size) {
    const float* x     = (const float*)d_in[0];
    const float* Wq    = (const float*)d_in[1];
    const float* Wk    = (const float*)d_in[2];
    const float* Wv    = (const float*)d_in[3];
    const float* Wproj = (const float*)d_in[4];
    const float* bproj = (const float*)d_in[5];
    const float* W1    = (const float*)d_in[6];
    const float* b1    = (const float*)d_in[7];
    const float* W2    = (const float*)d_in[8];
    const float* b2    = (const float*)d_in[9];
    const float* g1    = (const float*)d_in[10];
    const float* be1   = (const float*)d_in[11];
    const float* g2    = (const float*)d_in[12];
    const float* be2   = (const float*)d_in[13];
    float* out = (float*)d_out;

    float *x2;
    __half *qkvh, *qkvl, *h1h, *h1l, *h2h, *h2l, *aoh, *aol, *midh, *midl;
    __half *wqkv, *wp, *w1, *w2;
    cudaGetSymbolAddress((void**)&x2,    g_x2);
    cudaGetSymbolAddress((void**)&qkvh,  g_qkvh);  cudaGetSymbolAddress((void**)&qkvl, g_qkvl);
    cudaGetSymbolAddress((void**)&h1h,   g_h1h);   cudaGetSymbolAddress((void**)&h1l,  g_h1l);
    cudaGetSymbolAddress((void**)&h2h,   g_h2h);   cudaGetSymbolAddress((void**)&h2l,  g_h2l);
    cudaGetSymbolAddress((void**)&aoh,   g_aoh);   cudaGetSymbolAddress((void**)&aol,  g_aol);
    cudaGetSymbolAddress((void**)&midh,  g_midh);  cudaGetSymbolAddress((void**)&midl, g_midl);
    cudaGetSymbolAddress((void**)&wqkv,  g_wqkv);
    cudaGetSymbolAddress((void**)&wp,    g_wp);
    cudaGetSymbolAddress((void**)&w1,    g_w1);
    cudaGetSymbolAddress((void**)&w2,    g_w2);

    const int GEMM_SMEM = 4 * 24576;   // 96KB, 4-stage ring
    cudaFuncSetAttribute(mma_gemm<1>, cudaFuncAttributeMaxDynamicSharedMemorySize, GEMM_SMEM);
    cudaFuncSetAttribute(mma_gemm<2>, cudaFuncAttributeMaxDynamicSharedMemorySize, GEMM_SMEM);
    cudaFuncSetAttribute(mma_gemm<3>, cudaFuncAttributeMaxDynamicSharedMemorySize, GEMM_SMEM);
    const int ATTN_SMEM = 32768 + 3 * 16384;   // Q 32KB + 3-stage KV ring 48KB
    cudaFuncSetAttribute(attn_mma, cudaFuncAttributeMaxDynamicSharedMemorySize, ATTN_SMEM);

    // weight packs (single fp16, [N,K] layout)
    pack_qkv_kernel<<<dim3(En / 32, QKVN / 32), dim3(32, 8)>>>(Wq, Wk, Wv, wqkv);
    pack_t_kernel<<<dim3(En / 32, En / 32),  dim3(32, 8)>>>(Wproj, wp, En, En);
    pack_t_kernel<<<dim3(En / 32, FFn / 32), dim3(32, 8)>>>(W1, w1, En, FFn);
    pack_t_kernel<<<dim3(FFn / 32, En / 32), dim3(32, 8)>>>(W2, w2, FFn, En);

    // LN1 -> h1 hi/lo
    ln_kernel<<<Mn, 256>>>(x, g1, be1, h1h, h1l);
    // QKV GEMM: -> qkv fp16 hi/lo
    mma_gemm<3><<<dim3(QKVN / 128, Mn / 128), 256, GEMM_SMEM>>>(
        h1h, h1l, wqkv, Mn, QKVN, En, nullptr, nullptr, nullptr, qkvh, qkvl);
    // flash attention -> attno hi/lo
    attn_mma<<<dim3(Tn / 128, Bn * Hn), 256, ATTN_SMEM>>>(qkvh, qkvl, aoh, aol);
    // proj + bias + residual(x) -> x2 fp32
    mma_gemm<1><<<dim3(En / 128, Mn / 128), 256, GEMM_SMEM>>>(
        aoh, aol, wp, Mn, En, En, bproj, x, x2, nullptr, nullptr);
    // LN2 -> h2 hi/lo
    ln_kernel<<<Mn, 256>>>(x2, g2, be2, h2h, h2l);
    // FFN1: relu(h2 @ W1 + b1) -> mid hi/lo
    mma_gemm<2><<<dim3(FFn / 128, Mn / 128), 256, GEMM_SMEM>>>(
        h2h, h2l, w1, Mn, FFn, En, b1, nullptr, nullptr, midh, midl);
    // FFN2: x2 + mid @ W2 + b2 -> out fp32
    mma_gemm<1><<<dim3(En / 128, Mn / 128), 256, GEMM_SMEM>>>(
        midh, midl, w2, Mn, En, FFn, b2, x2, out, nullptr, nullptr);
}

// round 7
// speedup vs baseline: 9.8696x; 1.8835x over previous
#include <cuda_runtime.h>
#include <cuda_fp16.h>
#include <cstdint>
#include <cstddef>

#define Bn 2
#define Tn 2048
#define En 1024
#define Hn 16
#define HDn 64
#define FFn 4096
#define Mn (Bn*Tn)          // 4096
#define QKVN (3*En)         // 3072

// ---------------- scratch (device globals) ----------------
__device__ float g_x2[(size_t)Mn*En];                       // 16 MB fp32
__device__ __half g_qkv[(size_t)Mn*QKVN];
__device__ __half g_h1[(size_t)Mn*En];
__device__ __half g_h2[(size_t)Mn*En];
__device__ __half g_ao[(size_t)Mn*En];
__device__ __half g_mid[(size_t)Mn*FFn];
__device__ __half g_wqkv[(size_t)QKVN*En];   // weights: fp16, [N,K]
__device__ __half g_wp[(size_t)En*En];
__device__ __half g_w1[(size_t)FFn*En];
__device__ __half g_w2[(size_t)En*FFn];

// ---------------- helpers ----------------
__device__ __forceinline__ uint32_t pack_h2(float a, float b) {
    __half2 H = __halves2half2(__float2half_rn(a), __float2half_rn(b));
    return *reinterpret_cast<uint32_t*>(&H);
}

__device__ __forceinline__ uint32_t s2u(const void* p) {
    uint32_t a;
    asm("{ .reg .u64 t; cvta.to.shared.u64 t, %1; cvt.u32.u64 %0, t; }" : "=r"(a) : "l"(p));
    return a;
}

__device__ __forceinline__ void cp16(uint32_t s, const void* g) {
    asm volatile("cp.async.cg.shared.global [%0], [%1], 16;" :: "r"(s), "l"(g));
}
#define CP_COMMIT() asm volatile("cp.async.commit_group;")
#define CP_WAIT(N)  asm volatile("cp.async.wait_group %0;" :: "n"(N))

#define LDM4(r, addr) \
    asm volatile("ldmatrix.sync.aligned.m8n8.x4.shared.b16 {%0,%1,%2,%3}, [%4];" \
        : "=r"((r)[0]), "=r"((r)[1]), "=r"((r)[2]), "=r"((r)[3]) : "r"(addr))

#define LDM4T(r, addr) \
    asm volatile("ldmatrix.sync.aligned.m8n8.x4.trans.shared.b16 {%0,%1,%2,%3}, [%4];" \
        : "=r"((r)[0]), "=r"((r)[1]), "=r"((r)[2]), "=r"((r)[3]) : "r"(addr))

#define MMA_F16(d, a, b0, b1) \
    asm volatile("mma.sync.aligned.m16n8k16.row.col.f32.f16.f16.f32 " \
        "{%0,%1,%2,%3}, {%4,%5,%6,%7}, {%8,%9}, {%0,%1,%2,%3};" \
        : "+f"((d)[0]), "+f"((d)[1]), "+f"((d)[2]), "+f"((d)[3]) \
        : "r"((a)[0]), "r"((a)[1]), "r"((a)[2]), "r"((a)[3]), "r"(b0), "r"(b1))

// fast exp2 for t <= 0 (degree-6 Taylor of 2^f, rel err ~1.5e-5), FMA pipe only
__device__ __forceinline__ float exp2f_fast(float t) {
    t = fmaxf(t, -126.0f);
    float fi = floorf(t);
    float f = t - fi;
    float p = 1.5403530e-4f;
    p = fmaf(p, f, 1.3333558e-3f);
    p = fmaf(p, f, 9.6181291e-3f);
    p = fmaf(p, f, 5.5504109e-2f);
    p = fmaf(p, f, 2.4022651e-1f);
    p = fmaf(p, f, 6.9314718e-1f);
    p = fmaf(p, f, 1.0f);
    return __int_as_float(__float_as_int(p) + ((int)fi << 23));
}

// ---------------- weight pack kernels (smem-tiled, fp16 out) ----------------
__global__ void pack_qkv_kernel(const float* __restrict__ Wq, const float* __restrict__ Wk,
                                const float* __restrict__ Wv, __half* __restrict__ o) {
    __shared__ float tile[32][33];
    int k0 = blockIdx.x * 32;
    int n0 = blockIdx.y * 32;
    int sel = n0 >> 10;
    int hc = n0 & 1023;
    int h = hc >> 6, e0 = hc & 63;
    const float* W = (sel == 0) ? Wq : (sel == 1) ? Wk : Wv;
    int tx = threadIdx.x, ty = threadIdx.y;
#pragma unroll
    for (int i = 0; i < 4; i++)
        tile[ty + 8 * i][tx] = W[((size_t)h * En + k0 + ty + 8 * i) * HDn + e0 + tx];
    __syncthreads();
#pragma unroll
    for (int i = 0; i < 4; i++) {
        int n = n0 + ty + 8 * i, k = k0 + tx;
        o[(size_t)n * En + k] = __float2half_rn(tile[tx][ty + 8 * i]);
    }
}

__global__ void pack_t_kernel(const float* __restrict__ In, __half* __restrict__ o,
                              int K, int N) {
    __shared__ float tile[32][33];
    int k0 = blockIdx.x * 32;
    int n0 = blockIdx.y * 32;
    int tx = threadIdx.x, ty = threadIdx.y;
#pragma unroll
    for (int i = 0; i < 4; i++)
        tile[ty + 8 * i][tx] = In[(size_t)(k0 + ty + 8 * i) * N + n0 + tx];
    __syncthreads();
#pragma unroll
    for (int i = 0; i < 4; i++) {
        int n = n0 + ty + 8 * i, k = k0 + tx;
        o[(size_t)n * K + k] = __float2half_rn(tile[tx][ty + 8 * i]);
    }
}

// ---------------- LayerNorm: fp32 in -> fp16 out ----------------
__global__ void ln_kernel(const float* __restrict__ x, const float* __restrict__ g,
                          const float* __restrict__ b, __half* __restrict__ o) {
    int row = blockIdx.x;
    const float* xr = x + (size_t)row * En;
    float v[4];
    float s = 0.f, sq = 0.f;
#pragma unroll
    for (int i = 0; i < 4; i++) {
        v[i] = xr[threadIdx.x + i * 256];
        s += v[i]; sq += v[i] * v[i];
    }
    __shared__ float red[18];
#pragma unroll
    for (int of = 16; of; of >>= 1) {
        s  += __shfl_xor_sync(0xFFFFFFFFu, s,  of);
        sq += __shfl_xor_sync(0xFFFFFFFFu, sq, of);
    }
    int w = threadIdx.x >> 5, l = threadIdx.x & 31;
    if (l == 0) { red[w] = s; red[8 + w] = sq; }
    __syncthreads();
    if (threadIdx.x == 0) {
        float ts = 0.f, tq = 0.f;
#pragma unroll
        for (int i = 0; i < 8; i++) { ts += red[i]; tq += red[8 + i]; }
        red[16] = ts; red[17] = tq;
    }
    __syncthreads();
    float mean = red[16] * (1.f / En);
    float var  = red[17] * (1.f / En) - mean * mean;
    float rstd = rsqrtf(var + 1e-5f);
#pragma unroll
    for (int i = 0; i < 4; i++) {
        int c = threadIdx.x + i * 256;
        float y = (v[i] - mean) * rstd * g[c] + b[c];
        o[(size_t)row * En + c] = __float2half_rn(y);
    }
}

// ---------------- mma.sync GEMM: C[M,N] = A[M,K] @ B^T ([N,K]), pure fp16 ----------------
// 128x128 CTA tile, BK=32, 4-stage cp.async ring (16KB/stage), ONE sync per stage.
// EPI: 1 = fp32 out + bias + residual; 2 = relu(+bias) -> fp16; 3 = fp16
template<int EPI>
__global__ void __launch_bounds__(256, 2)
mma_gemm(const __half* __restrict__ A, const __half* __restrict__ B,
         int M, int N, int K,
         const float* __restrict__ bias, const float* __restrict__ res,
         float* __restrict__ Cf, __half* __restrict__ Ch) {
    extern __shared__ __align__(1024) char smem[];
    const uint32_t su = s2u(smem);
    const int tid = threadIdx.x;
    const int lane = tid & 31, wid = tid >> 5;
    const int warp_m = wid & 1, warp_n = wid >> 1;
    const int brow = blockIdx.y * 128, bcol = blockIdx.x * 128;
    const int S = K >> 5;      // stages of BK=32

    const int mat = lane >> 3, rowm = lane & 7;
    const int c16bA = mat >> 1;
    const int c16bB = mat & 1;
    uint32_t mrow64[4], swmA[4];
#pragma unroll
    for (int mi = 0; mi < 4; mi++) {
        int m = warp_m * 64 + mi * 16 + (mat & 1) * 8 + rowm;
        mrow64[mi] = (uint32_t)(m * 64);
        swmA[mi] = (uint32_t)(((m >> 1) & 7) << 4);
    }
    uint32_t nrow64[2], swmB[2];
#pragma unroll
    for (int nj = 0; nj < 2; nj++) {
        int n = warp_n * 32 + nj * 16 + (mat >> 1) * 8 + rowm;
        nrow64[nj] = (uint32_t)(n * 64);
        swmB[nj] = (uint32_t)(((n >> 1) & 7) << 4);
    }

    float acc[4][4][4];
#pragma unroll
    for (int mi = 0; mi < 4; mi++)
#pragma unroll
        for (int j = 0; j < 4; j++)
#pragma unroll
            for (int r = 0; r < 4; r++) acc[mi][j][r] = 0.f;

    // stage: A@0 (8K), B@8192; 16KB per stage
    auto load_stage = [&](int s) {
        const int k0 = s * 32;
        const uint32_t sb = su + (uint32_t)(s & 3) * 16384;
#pragma unroll
        for (int i = 0; i < 4; i++) {
            int idx = tid + i * 256;          // 0..1023
            int tns = idx >> 9;               // 0=A 1=B
            int sub = idx & 511;
            int r = sub >> 2, c = sub & 3;
            uint32_t o = (uint32_t)(r * 64 + c * 16);
            uint32_t sw = o ^ (((o >> 7) & 7) << 4);
            const __half* src = (tns == 0) ? A + (size_t)(brow + r) * K + k0 + c * 8
                                           : B + (size_t)(bcol + r) * K + k0 + c * 8;
            cp16(sb + (uint32_t)tns * 8192 + sw, src);
        }
    };

    // prologue: 3 stages in flight
#pragma unroll
    for (int s = 0; s < 3; s++) { load_stage(s); CP_COMMIT(); }

    for (int s = 0; s < S; s++) {
        CP_WAIT(2);
        __syncthreads();
        if (s + 3 < S) load_stage(s + 3);
        CP_COMMIT();

        const uint32_t sb = su + (uint32_t)(s & 3) * 16384;
#pragma unroll
        for (int kk = 0; kk < 2; kk++) {
            uint32_t ah[4][4];
            const int cA = kk * 2 + c16bA;
#pragma unroll
            for (int mi = 0; mi < 4; mi++) {
                uint32_t oa = (mrow64[mi] + (uint32_t)(cA * 16)) ^ swmA[mi];
                LDM4(ah[mi], sb + oa);
            }
            uint32_t bh[2][4];
            const int cB = kk * 2 + c16bB;
#pragma unroll
            for (int nj = 0; nj < 2; nj++) {
                uint32_t ob = (nrow64[nj] + (uint32_t)(cB * 16)) ^ swmB[nj];
                LDM4(bh[nj], sb + 8192 + ob);
            }
#pragma unroll
            for (int mi = 0; mi < 4; mi++) {
#pragma unroll
                for (int j = 0; j < 4; j++) {
                    const int nj = j >> 1, rb = (j & 1) * 2;
                    MMA_F16(acc[mi][j], ah[mi], bh[nj][rb], bh[nj][rb + 1]);
                }
            }
        }
    }

    // ---------------- epilogue ----------------
    const int rowbase = brow + warp_m * 64 + (lane >> 2);
    const int colbase = bcol + warp_n * 32 + (lane & 3) * 2;
#pragma unroll
    for (int mi = 0; mi < 4; mi++) {
#pragma unroll
        for (int j = 0; j < 4; j++) {
            int col = colbase + j * 8;
            int r0 = rowbase + mi * 16;
            int r1 = r0 + 8;
            float v00 = acc[mi][j][0], v01 = acc[mi][j][1];
            float v10 = acc[mi][j][2], v11 = acc[mi][j][3];
            if (EPI == 1) {
                float b0 = bias[col], b1 = bias[col + 1];
                const float2 rr0 = *(const float2*)(res + (size_t)r0 * N + col);
                const float2 rr1 = *(const float2*)(res + (size_t)r1 * N + col);
                *(float2*)(Cf + (size_t)r0 * N + col) = make_float2(v00 + b0 + rr0.x, v01 + b1 + rr0.y);
                *(float2*)(Cf + (size_t)r1 * N + col) = make_float2(v10 + b0 + rr1.x, v11 + b1 + rr1.y);
            } else if (EPI == 2) {
                float b0 = bias[col], b1 = bias[col + 1];
                *(uint32_t*)(Ch + (size_t)r0 * N + col) =
                    pack_h2(fmaxf(v00 + b0, 0.f), fmaxf(v01 + b1, 0.f));
                *(uint32_t*)(Ch + (size_t)r1 * N + col) =
                    pack_h2(fmaxf(v10 + b0, 0.f), fmaxf(v11 + b1, 0.f));
            } else {  // EPI == 3: raw fp16
                *(uint32_t*)(Ch + (size_t)r0 * N + col) = pack_h2(v00, v01);
                *(uint32_t*)(Ch + (size_t)r1 * N + col) = pack_h2(v10, v11);
            }
        }
    }
}

// ---------------- mma.sync flash attention (causal, scale = 1/32), pure fp16 ----------------
// Q tile 128 x HD64 per CTA; 8 warps x 16 query rows; key chunks of 64,
// 3-stage cp.async KV ring (K+V = 16KB/chunk), ONE sync per chunk.
__global__ void __launch_bounds__(256, 1)
attn_mma(const __half* __restrict__ qkv, __half* __restrict__ outp) {
    extern __shared__ __align__(1024) char smem[];
    const uint32_t su = s2u(smem);
    const int tid = threadIdx.x, lane = tid & 31, w = tid >> 5;
    const int mat = lane >> 3, rowm = lane & 7;
    const uint32_t swx = (uint32_t)rowm << 4;

    const int tile = (Tn / 128 - 1) - blockIdx.x;   // biggest tiles first
    const int bh = blockIdx.y, b = bh >> 4, h = bh & 15;
    const int q0 = tile * 128;
    const int nch = 2 * (tile + 1);
    const size_t RS = QKVN;

    const __half* Qg = qkv + ((size_t)b * Tn + q0) * RS + h * HDn;
    const __half* Kg = qkv + (size_t)b * Tn * RS + En + h * HDn;
    const __half* Vg = qkv + (size_t)b * Tn * RS + 2 * En + h * HDn;

    // Q tile (128 x 64 fp16) -> smem [0, 16KB)
#pragma unroll
    for (int i = 0; i < 4; i++) {
        int idx = tid + i * 256;      // 0..1023
        int r = idx >> 3;
        int c = idx & 7;
        uint32_t o = (uint32_t)(r * 128 + c * 16);
        uint32_t sw = o ^ (uint32_t)((r & 7) << 4);
        cp16(su + sw, Qg + (size_t)r * RS + c * 8);
    }
    CP_COMMIT();

    // KV ring: 3 slots of 16KB (K 8KB + V 8KB) at su+16384
    auto loadKV = [&](int j) {
        const int j0 = j * 64;
        const uint32_t sb = su + 16384 + (uint32_t)(j % 3) * 16384;
#pragma unroll
        for (int i = 0; i < 4; i++) {
            int idx = tid + i * 256;   // 0..1023
            int tns = idx >> 9;        // 0=K 1=V
            int sub = idx & 511;
            int r = sub >> 3, c = sub & 7;
            uint32_t o = (uint32_t)(r * 128 + c * 16);
            uint32_t sw = o ^ (uint32_t)((r & 7) << 4);
            size_t go = (size_t)(j0 + r) * RS + c * 8;
            const __half* src = (tns == 0) ? Kg + go : Vg + go;
            cp16(sb + (uint32_t)tns * 8192 + sw, src);
        }
    };
    loadKV(0);
    CP_COMMIT();
    loadKV(1);                // nch >= 2 always
    CP_COMMIT();
    CP_WAIT(2);               // Q complete
    __syncthreads();

    // Q fragments (persist): 4 k-steps x 4 regs
    uint32_t qf[4][4];
    {
        int m = w * 16 + (mat & 1) * 8 + rowm;
#pragma unroll
        for (int s = 0; s < 4; s++) {
            uint32_t o = ((uint32_t)(m * 128 + s * 32 + (mat >> 1) * 16)) ^ swx;
            LDM4(qf[s], su + o);
        }
    }

    float O[8][4];
#pragma unroll
    for (int a = 0; a < 8; a++)
#pragma unroll
        for (int r = 0; r < 4; r++) O[a][r] = 0.f;
    float m0 = -1e30f, m1 = -1e30f, l0 = 0.f, l1 = 0.f;

    const int rmin = q0 + w * 16;
    const int r0g = rmin + (lane >> 2), r1g = r0g + 8;
    const float SCL = 0.04508422f;   // log2(e) / 32

    for (int j = 0; j < nch; j++) {
        CP_WAIT(1);
        __syncthreads();
        if (j + 2 < nch) loadKV(j + 2);
        CP_COMMIT();

        const int j0 = j * 64;
        if (j0 <= rmin + 15) {
            const uint32_t sb = su + 16384 + (uint32_t)(j % 3) * 16384;

            // ---- S = Q K^T ----
            float S[8][4];
#pragma unroll
            for (int jt = 0; jt < 8; jt++)
#pragma unroll
                for (int r = 0; r < 4; r++) S[jt][r] = 0.f;
#pragma unroll
            for (int s = 0; s < 4; s++) {
                uint32_t kh4[4][4];
#pragma unroll
                for (int nb = 0; nb < 4; nb++) {
                    int n = nb * 16 + (mat >> 1) * 8 + rowm;
                    uint32_t o = ((uint32_t)(n * 128 + s * 32 + (mat & 1) * 16)) ^ swx;
                    LDM4(kh4[nb], sb + o);
                }
#pragma unroll
                for (int nb = 0; nb < 4; nb++) {
#pragma unroll
                    for (int hf = 0; hf < 2; hf++) {
                        int jt = nb * 2 + hf;
                        MMA_F16(S[jt], qf[s], kh4[nb][hf * 2], kh4[nb][hf * 2 + 1]);
                    }
                }
            }

            // ---- scale (to log2 domain) + causal mask ----
#pragma unroll
            for (int jt = 0; jt < 8; jt++) {
                S[jt][0] *= SCL; S[jt][1] *= SCL; S[jt][2] *= SCL; S[jt][3] *= SCL;
            }
            if (j0 + 63 > rmin) {
#pragma unroll
                for (int jt = 0; jt < 8; jt++) {
                    int c0 = j0 + jt * 8 + 2 * (lane & 3);
                    if (c0 > r0g)     S[jt][0] = -1e30f;
                    if (c0 + 1 > r0g) S[jt][1] = -1e30f;
                    if (c0 > r1g)     S[jt][2] = -1e30f;
                    if (c0 + 1 > r1g) S[jt][3] = -1e30f;
                }
            }

            // ---- online softmax (base-2) ----
            float mx0 = -1e30f, mx1 = -1e30f;
#pragma unroll
            for (int jt = 0; jt < 8; jt++) {
                mx0 = fmaxf(mx0, fmaxf(S[jt][0], S[jt][1]));
                mx1 = fmaxf(mx1, fmaxf(S[jt][2], S[jt][3]));
            }
            mx0 = fmaxf(mx0, __shfl_xor_sync(0xFFFFFFFFu, mx0, 1));
            mx0 = fmaxf(mx0, __shfl_xor_sync(0xFFFFFFFFu, mx0, 2));
            mx1 = fmaxf(mx1, __shfl_xor_sync(0xFFFFFFFFu, mx1, 1));
            mx1 = fmaxf(mx1, __shfl_xor_sync(0xFFFFFFFFu, mx1, 2));
            float mn0 = fmaxf(m0, mx0), mn1 = fmaxf(m1, mx1);
            float al0 = exp2f_fast(m0 - mn0), al1 = exp2f_fast(m1 - mn1);
            m0 = mn0; m1 = mn1;
            float s0 = 0.f, s1 = 0.f;
#pragma unroll
            for (int jt = 0; jt < 8; jt++) {
                float p0 = exp2f_fast(S[jt][0] - mn0); S[jt][0] = p0;
                float p1 = exp2f_fast(S[jt][1] - mn0); S[jt][1] = p1;
                float p2 = exp2f_fast(S[jt][2] - mn1); S[jt][2] = p2;
                float p3 = exp2f_fast(S[jt][3] - mn1); S[jt][3] = p3;
                s0 += p0 + p1; s1 += p2 + p3;
            }
            s0 += __shfl_xor_sync(0xFFFFFFFFu, s0, 1);
            s0 += __shfl_xor_sync(0xFFFFFFFFu, s0, 2);
            s1 += __shfl_xor_sync(0xFFFFFFFFu, s1, 1);
            s1 += __shfl_xor_sync(0xFFFFFFFFu, s1, 2);
            l0 = l0 * al0 + s0;
            l1 = l1 * al1 + s1;
#pragma unroll
            for (int dt = 0; dt < 8; dt++) {
                O[dt][0] *= al0; O[dt][1] *= al0; O[dt][2] *= al1; O[dt][3] *= al1;
            }

            // ---- O += P V ----
#pragma unroll
            for (int s = 0; s < 4; s++) {
                const int t0 = 2 * s, t1 = 2 * s + 1;
                uint32_t ph[4];
                ph[0] = pack_h2(S[t0][0], S[t0][1]);
                ph[1] = pack_h2(S[t0][2], S[t0][3]);
                ph[2] = pack_h2(S[t1][0], S[t1][1]);
                ph[3] = pack_h2(S[t1][2], S[t1][3]);
                uint32_t vh4[4][4];
#pragma unroll
                for (int nb = 0; nb < 4; nb++) {
                    int kr = s * 16 + (mat & 1) * 8 + rowm;
                    uint32_t o = ((uint32_t)(kr * 128 + (nb * 16 + (mat >> 1) * 8) * 2)) ^ swx;
                    LDM4T(vh4[nb], sb + 8192 + o);
                }
#pragma unroll
                for (int nb = 0; nb < 4; nb++) {
#pragma unroll
                    for (int hf = 0; hf < 2; hf++) {
                        int dt = nb * 2 + hf;
                        MMA_F16(O[dt], ph, vh4[nb][hf * 2], vh4[nb][hf * 2 + 1]);
                    }
                }
            }
        }
    }

    // ---- normalize + store fp16 ----
    float inv0 = 1.f / l0, inv1 = 1.f / l1;
#pragma unroll
    for (int dt = 0; dt < 8; dt++) {
        int col = h * 64 + dt * 8 + 2 * (lane & 3);
        size_t o0 = ((size_t)b * Tn + r0g) * En + col;
        size_t o1 = ((size_t)b * Tn + r1g) * En + col;
        *(uint32_t*)(outp + o0) = pack_h2(O[dt][0] * inv0, O[dt][1] * inv0);
        *(uint32_t*)(outp + o1) = pack_h2(O[dt][2] * inv1, O[dt][3] * inv1);
    }
}

// ---------------- launch ----------------
extern "C" void kernel_launch(void* const* d_in, const int* in_sizes, int n_in,
                              void* d_out, int out_size) {
    const float* x     = (const float*)d_in[0];
    const float* Wq    = (const float*)d_in[1];
    const float* Wk    = (const float*)d_in[2];
    const float* Wv    = (const float*)d_in[3];
    const float* Wproj = (const float*)d_in[4];
    const float* bproj = (const float*)d_in[5];
    const float* W1    = (const float*)d_in[6];
    const float* b1    = (const float*)d_in[7];
    const float* W2    = (const float*)d_in[8];
    const float* b2    = (const float*)d_in[9];
    const float* g1    = (const float*)d_in[10];
    const float* be1   = (const float*)d_in[11];
    const float* g2    = (const float*)d_in[12];
    const float* be2   = (const float*)d_in[13];
    float* out = (float*)d_out;

    float *x2;
    __half *qkv, *h1, *h2, *ao, *mid, *wqkv, *wp, *w1, *w2;
    cudaGetSymbolAddress((void**)&x2,   g_x2);
    cudaGetSymbolAddress((void**)&qkv,  g_qkv);
    cudaGetSymbolAddress((void**)&h1,   g_h1);
    cudaGetSymbolAddress((void**)&h2,   g_h2);
    cudaGetSymbolAddress((void**)&ao,   g_ao);
    cudaGetSymbolAddress((void**)&mid,  g_mid);
    cudaGetSymbolAddress((void**)&wqkv, g_wqkv);
    cudaGetSymbolAddress((void**)&wp,   g_wp);
    cudaGetSymbolAddress((void**)&w1,   g_w1);
    cudaGetSymbolAddress((void**)&w2,   g_w2);

    const int GEMM_SMEM = 4 * 16384;   // 64KB, 4-stage ring (2 CTAs/SM)
    cudaFuncSetAttribute(mma_gemm<1>, cudaFuncAttributeMaxDynamicSharedMemorySize, GEMM_SMEM);
    cudaFuncSetAttribute(mma_gemm<2>, cudaFuncAttributeMaxDynamicSharedMemorySize, GEMM_SMEM);
    cudaFuncSetAttribute(mma_gemm<3>, cudaFuncAttributeMaxDynamicSharedMemorySize, GEMM_SMEM);
    const int ATTN_SMEM = 16384 + 3 * 16384;   // Q 16KB + 3-stage KV ring 48KB
    cudaFuncSetAttribute(attn_mma, cudaFuncAttributeMaxDynamicSharedMemorySize, ATTN_SMEM);

    // weight packs (fp16, [N,K] layout)
    pack_qkv_kernel<<<dim3(En / 32, QKVN / 32), dim3(32, 8)>>>(Wq, Wk, Wv, wqkv);
    pack_t_kernel<<<dim3(En / 32, En / 32),  dim3(32, 8)>>>(Wproj, wp, En, En);
    pack_t_kernel<<<dim3(En / 32, FFn / 32), dim3(32, 8)>>>(W1, w1, En, FFn);
    pack_t_kernel<<<dim3(FFn / 32, En / 32), dim3(32, 8)>>>(W2, w2, FFn, En);

    // LN1 -> h1 fp16
    ln_kernel<<<Mn, 256>>>(x, g1, be1, h1);
    // QKV GEMM -> qkv fp16
    mma_gemm<3><<<dim3(QKVN / 128, Mn / 128), 256, GEMM_SMEM>>>(
        h1, wqkv, Mn, QKVN, En, nullptr, nullptr, nullptr, qkv);
    // flash attention -> ao fp16
    attn_mma<<<dim3(Tn / 128, Bn * Hn), 256, ATTN_SMEM>>>(qkv, ao);
    // proj + bias + residual(x) -> x2 fp32
    mma_gemm<1><<<dim3(En / 128, Mn / 128), 256, GEMM_SMEM>>>(
        ao, wp, Mn, En, En, bproj, x, x2, nullptr);
    // LN2 -> h2 fp16
    ln_kernel<<<Mn, 256>>>(x2, g2, be2, h2);
    // FFN1: relu(h2 @ W1 + b1) -> mid fp16
    mma_gemm<2><<<dim3(FFn / 128, Mn / 128), 256, GEMM_SMEM>>>(
        h2, w1, Mn, FFn, En, b1, nullptr, nullptr, mid);
    // FFN2: x2 + mid @ W2 + b2 -> out fp32
    mma_gemm<1><<<dim3(En / 128, Mn / 128), 256, GEMM_SMEM>>>(
        mid, w2, Mn, En, FFn, b2, x2, out, nullptr);
}